// round 1
// baseline (speedup 1.0000x reference)
#include <cuda_runtime.h>
#include <cstdint>

// Problem constants
// B=8, NS=NT=1024, SRC=TGT=OUT=1024, H=8, DH=128
#define Bsz 8
#define NSEQ 1024
#define OUTD 1024
#define HH 8
#define DHD 128

#define DINLINE __device__ __forceinline__

// ---------------- scratch (allocation-free rule: __device__ globals) ----------
__device__ __align__(16) float g_kv [8u*1024u*2048u];   // src_trans [B,NS,2*OUT] (key|val)
__device__ __align__(16) float g_q  [8u*1024u*1024u];   // tgt_trans [B,NT,OUT]
__device__ __align__(16) float g_upd[8u*1024u*1024u];   // tgt_update [B,NT,OUT]

// ---------------- helpers ------------------------------------------------------
DINLINE uint32_t f2tf(float x) {
    uint32_t r;
    asm("cvt.rna.tf32.f32 %0, %1;" : "=r"(r) : "f"(x));
    return r;
}
DINLINE float f2tff(float x) { return __uint_as_float(f2tf(x)); }

DINLINE void mma_tf32(float c[4], const uint32_t a[4], const uint32_t b[2]) {
    asm volatile(
        "mma.sync.aligned.m16n8k8.row.col.f32.tf32.tf32.f32 "
        "{%0,%1,%2,%3}, {%4,%5,%6,%7}, {%8,%9}, {%0,%1,%2,%3};"
        : "+f"(c[0]), "+f"(c[1]), "+f"(c[2]), "+f"(c[3])
        : "r"(a[0]), "r"(a[1]), "r"(a[2]), "r"(a[3]), "r"(b[0]), "r"(b[1]));
}

// ================================================================================
// GEMM: C[M,N] = A[M,K] @ W[N,K]^T, optional +bias[n], *rowmask[m], +=C (accumulate)
// Tiles: BM=128, BN=128, BK=32. 256 threads, 8 warps (2m x 4n), warp tile 64x32.
// All dims assumed divisible (M=8192, N in {1024,2048}, K=1024).
// Inputs converted to tf32 (cvt.rna) on the global->shared path.
// ================================================================================
__global__ __launch_bounds__(256)
void gemm_tf32(const float* __restrict__ A, int lda,
               const float* __restrict__ W, int ldw,
               const float* __restrict__ bias,
               const float* __restrict__ rowmask,
               float* __restrict__ C, int ldc,
               int K, int accumulate)
{
    extern __shared__ float sm[];
    float* As = sm;                 // [2][128][36]
    float* Bs = sm + 2 * 128 * 36;  // [2][128][36]

    const int tid  = threadIdx.x;
    const int lane = tid & 31;
    const int wid  = tid >> 5;
    const int wm   = wid & 1;     // 0..1
    const int wn   = wid >> 1;    // 0..3
    const int g    = lane >> 2;   // groupID 0..7
    const int tg   = lane & 3;    // thread-in-group 0..3

    const int mBase = blockIdx.y * 128;
    const int nBase = blockIdx.x * 128;

    const int lrow = tid >> 3;    // 0..31 (4 rows covered, stride 32)
    const int lc4  = tid & 7;     // 0..7 float4 within 32-col row
    const float* gA = A + (size_t)(mBase + lrow) * lda + lc4 * 4;
    const float* gW = W + (size_t)(nBase + lrow) * ldw + lc4 * 4;

    float4 ra[4], rw[4];
    float acc[4][4][4];
#pragma unroll
    for (int i = 0; i < 4; i++)
#pragma unroll
        for (int j = 0; j < 4; j++)
#pragma unroll
            for (int k = 0; k < 4; k++) acc[i][j][k] = 0.f;

    const int nkb = K >> 5;

    auto LOAD = [&](int kb) {
        const float* pa = gA + kb * 32;
        const float* pw = gW + kb * 32;
#pragma unroll
        for (int i = 0; i < 4; i++) {
            ra[i] = *(const float4*)(pa + (size_t)(i * 32) * lda);
            rw[i] = *(const float4*)(pw + (size_t)(i * 32) * ldw);
        }
    };
    auto STORE = [&](int st) {
        float* as = As + st * 128 * 36;
        float* bs = Bs + st * 128 * 36;
#pragma unroll
        for (int i = 0; i < 4; i++) {
            int r = lrow + i * 32;
            float4 v = ra[i];
            v.x = f2tff(v.x); v.y = f2tff(v.y); v.z = f2tff(v.z); v.w = f2tff(v.w);
            *(float4*)(as + r * 36 + lc4 * 4) = v;
            float4 u = rw[i];
            u.x = f2tff(u.x); u.y = f2tff(u.y); u.z = f2tff(u.z); u.w = f2tff(u.w);
            *(float4*)(bs + r * 36 + lc4 * 4) = u;
        }
    };
    auto COMPUTE = [&](int st) {
        const float* as = As + st * 128 * 36;
        const float* bs = Bs + st * 128 * 36;
#pragma unroll
        for (int ks = 0; ks < 4; ks++) {
            const int kc = ks * 8 + tg;
            uint32_t af[4][4], bf[4][2];
#pragma unroll
            for (int mt = 0; mt < 4; mt++) {
                int r = wm * 64 + mt * 16 + g;
                af[mt][0] = __float_as_uint(as[r * 36 + kc]);
                af[mt][1] = __float_as_uint(as[(r + 8) * 36 + kc]);
                af[mt][2] = __float_as_uint(as[r * 36 + kc + 4]);
                af[mt][3] = __float_as_uint(as[(r + 8) * 36 + kc + 4]);
            }
#pragma unroll
            for (int nt = 0; nt < 4; nt++) {
                int n = wn * 32 + nt * 8 + g;
                bf[nt][0] = __float_as_uint(bs[n * 36 + kc]);
                bf[nt][1] = __float_as_uint(bs[n * 36 + kc + 4]);
            }
#pragma unroll
            for (int mt = 0; mt < 4; mt++)
#pragma unroll
                for (int nt = 0; nt < 4; nt++)
                    mma_tf32(acc[mt][nt], af[mt], bf[nt]);
        }
    };

    LOAD(0);
    STORE(0);
    __syncthreads();
    for (int kb = 0; kb < nkb; kb++) {
        if (kb + 1 < nkb) LOAD(kb + 1);
        COMPUTE(kb & 1);
        if (kb + 1 < nkb) STORE((kb + 1) & 1);
        __syncthreads();
    }

    // epilogue
#pragma unroll
    for (int mt = 0; mt < 4; mt++) {
        int r0 = mBase + wm * 64 + mt * 16 + g;
        float mk0 = rowmask ? rowmask[r0]     : 1.f;
        float mk1 = rowmask ? rowmask[r0 + 8] : 1.f;
#pragma unroll
        for (int nt = 0; nt < 4; nt++) {
            int c = nBase + wn * 32 + nt * 8 + 2 * tg;
            float b0 = bias ? bias[c]     : 0.f;
            float b1 = bias ? bias[c + 1] : 0.f;
            float v00 = (acc[mt][nt][0] + b0) * mk0;
            float v01 = (acc[mt][nt][1] + b1) * mk0;
            float v10 = (acc[mt][nt][2] + b0) * mk1;
            float v11 = (acc[mt][nt][3] + b1) * mk1;
            float* p0 = C + (size_t)r0 * ldc + c;
            float* p1 = C + (size_t)(r0 + 8) * ldc + c;
            if (accumulate) {
                float2 o0 = *(float2*)p0, o1 = *(float2*)p1;
                v00 += o0.x; v01 += o0.y; v10 += o1.x; v11 += o1.y;
            }
            *(float2*)p0 = make_float2(v00, v01);
            *(float2*)p1 = make_float2(v10, v11);
        }
    }
}

// ================================================================================
// Flash attention: per (b,h): O[t,d] = softmax(Q K^T / sqrt(128)) V
// Q = g_q head slice, K/V = g_kv head slices. BM=128 (8 warps x 16 rows),
// BN=64 kv chunk, DH=128. tf32 mma for both matmuls; p round-trips smem.
// Grid: (NT/128, B*H). 256 threads.
// ================================================================================
__global__ __launch_bounds__(256)
void attn_kernel(const float* __restrict__ Q, const float* __restrict__ KV,
                 const float* __restrict__ smask, float* __restrict__ O)
{
    extern __shared__ float sm[];
    float* q_s = sm;                   // [128][132]
    float* k_s = q_s + 128 * 132;      // [64][132]
    float* v_s = k_s + 64 * 132;       // [64][136]
    float* p_s = v_s + 64 * 136;       // [128][68]
    float* msk = p_s + 128 * 68;       // [64]

    const int tid  = threadIdx.x;
    const int lane = tid & 31;
    const int w    = tid >> 5;       // warp 0..7 -> rows 16w..16w+15
    const int g    = lane >> 2;
    const int tg   = lane & 3;

    const int bh = blockIdx.y;
    const int b  = bh >> 3;
    const int h  = bh & 7;
    const int t0 = blockIdx.x * 128;

    const float* qg = Q + ((size_t)b * NSEQ + t0) * OUTD + h * DHD;
    const float* kg = KV + (size_t)b * NSEQ * (2 * OUTD) + h * DHD;
    const float* vg = kg + OUTD;

    // load Q tile 128x128 (tf32-rounded)
#pragma unroll
    for (int i = 0; i < 16; i++) {
        int idx = tid + i * 256;
        int row = idx >> 5, c4 = idx & 31;
        float4 v = *(const float4*)(qg + (size_t)row * OUTD + c4 * 4);
        v.x = f2tff(v.x); v.y = f2tff(v.y); v.z = f2tff(v.z); v.w = f2tff(v.w);
        *(float4*)(q_s + row * 132 + c4 * 4) = v;
    }

    float oacc[16][4];
#pragma unroll
    for (int nt = 0; nt < 16; nt++)
#pragma unroll
        for (int i = 0; i < 4; i++) oacc[nt][i] = 0.f;
    float m0 = -1e30f, m1 = -1e30f, l0 = 0.f, l1 = 0.f;

    const float sc = 0.0883883476483184405f; // 1/sqrt(128)

    for (int j = 0; j < NSEQ / 64; j++) {
        __syncthreads();  // also covers Q tile on j==0
        // load K,V chunk 64x128 each
#pragma unroll
        for (int i = 0; i < 8; i++) {
            int idx = tid + i * 256;
            int row = idx >> 5, c4 = idx & 31;
            size_t go = (size_t)(j * 64 + row) * (2 * OUTD) + c4 * 4;
            float4 kk = *(const float4*)(kg + go);
            float4 vv = *(const float4*)(vg + go);
            kk.x = f2tff(kk.x); kk.y = f2tff(kk.y); kk.z = f2tff(kk.z); kk.w = f2tff(kk.w);
            vv.x = f2tff(vv.x); vv.y = f2tff(vv.y); vv.z = f2tff(vv.z); vv.w = f2tff(vv.w);
            *(float4*)(k_s + row * 132 + c4 * 4) = kk;
            *(float4*)(v_s + row * 136 + c4 * 4) = vv;
        }
        if (tid < 64) msk[tid] = smask[(size_t)b * NSEQ + j * 64 + tid];
        __syncthreads();

        // S = Q @ K^T  (rows 16w..16w+15, cols 0..63)
        float sacc[8][4];
#pragma unroll
        for (int nt = 0; nt < 8; nt++)
#pragma unroll
            for (int i = 0; i < 4; i++) sacc[nt][i] = 0.f;

#pragma unroll
        for (int ks = 0; ks < 16; ks++) {
            const int kc = ks * 8 + tg;
            const int r = w * 16 + g;
            uint32_t a[4];
            a[0] = __float_as_uint(q_s[r * 132 + kc]);
            a[1] = __float_as_uint(q_s[(r + 8) * 132 + kc]);
            a[2] = __float_as_uint(q_s[r * 132 + kc + 4]);
            a[3] = __float_as_uint(q_s[(r + 8) * 132 + kc + 4]);
#pragma unroll
            for (int nt = 0; nt < 8; nt++) {
                int srow = nt * 8 + g;
                uint32_t bb[2];
                bb[0] = __float_as_uint(k_s[srow * 132 + kc]);
                bb[1] = __float_as_uint(k_s[srow * 132 + kc + 4]);
                mma_tf32(sacc[nt], a, bb);
            }
        }

        // scale + mask + row max
        float rmax0 = -1e30f, rmax1 = -1e30f;
#pragma unroll
        for (int nt = 0; nt < 8; nt++) {
#pragma unroll
            for (int i = 0; i < 4; i++) {
                float s = sacc[nt][i] * sc;
                int col = nt * 8 + 2 * tg + (i & 1);
                if (msk[col] == 0.f) s = -1e30f;
                sacc[nt][i] = s;
                if (i < 2) rmax0 = fmaxf(rmax0, s);
                else       rmax1 = fmaxf(rmax1, s);
            }
        }
        rmax0 = fmaxf(rmax0, __shfl_xor_sync(0xffffffffu, rmax0, 1));
        rmax0 = fmaxf(rmax0, __shfl_xor_sync(0xffffffffu, rmax0, 2));
        rmax1 = fmaxf(rmax1, __shfl_xor_sync(0xffffffffu, rmax1, 1));
        rmax1 = fmaxf(rmax1, __shfl_xor_sync(0xffffffffu, rmax1, 2));

        float mn0 = fmaxf(m0, rmax0), mn1 = fmaxf(m1, rmax1);
        float cf0 = __expf(m0 - mn0), cf1 = __expf(m1 - mn1);
        m0 = mn0; m1 = mn1;

        // p = exp(s - m), store tf32 to p_s, rowsum
        float rs0 = 0.f, rs1 = 0.f;
        const int pr = w * 16 + g;
#pragma unroll
        for (int nt = 0; nt < 8; nt++) {
            float p0 = __expf(sacc[nt][0] - mn0);
            float p1 = __expf(sacc[nt][1] - mn0);
            float p2 = __expf(sacc[nt][2] - mn1);
            float p3 = __expf(sacc[nt][3] - mn1);
            rs0 += p0 + p1; rs1 += p2 + p3;
            int pc = nt * 8 + 2 * tg;
            *(float2*)(p_s + pr * 68 + pc)       = make_float2(f2tff(p0), f2tff(p1));
            *(float2*)(p_s + (pr + 8) * 68 + pc) = make_float2(f2tff(p2), f2tff(p3));
        }
        rs0 += __shfl_xor_sync(0xffffffffu, rs0, 1);
        rs0 += __shfl_xor_sync(0xffffffffu, rs0, 2);
        rs1 += __shfl_xor_sync(0xffffffffu, rs1, 1);
        rs1 += __shfl_xor_sync(0xffffffffu, rs1, 2);
        l0 = l0 * cf0 + rs0;
        l1 = l1 * cf1 + rs1;

        // rescale O accumulators
#pragma unroll
        for (int nt = 0; nt < 16; nt++) {
            oacc[nt][0] *= cf0; oacc[nt][1] *= cf0;
            oacc[nt][2] *= cf1; oacc[nt][3] *= cf1;
        }
        __syncwarp();

        // O += P @ V
#pragma unroll
        for (int ks = 0; ks < 8; ks++) {
            const int kc = ks * 8 + tg;
            uint32_t a[4];
            a[0] = __float_as_uint(p_s[pr * 68 + kc]);
            a[1] = __float_as_uint(p_s[(pr + 8) * 68 + kc]);
            a[2] = __float_as_uint(p_s[pr * 68 + kc + 4]);
            a[3] = __float_as_uint(p_s[(pr + 8) * 68 + kc + 4]);
            const int sr = ks * 8 + tg;
#pragma unroll
            for (int nt = 0; nt < 16; nt++) {
                int dc = nt * 8 + g;
                uint32_t bb[2];
                bb[0] = __float_as_uint(v_s[sr * 136 + dc]);
                bb[1] = __float_as_uint(v_s[(sr + 4) * 136 + dc]);
                mma_tf32(oacc[nt], a, bb);
            }
        }
    }

    // write out: O / l
    float inv0 = 1.f / l0, inv1 = 1.f / l1;
    const int tr0 = t0 + w * 16 + g;
    float* og = O + (size_t)b * NSEQ * OUTD + h * DHD;
#pragma unroll
    for (int nt = 0; nt < 16; nt++) {
        int dc = nt * 8 + 2 * tg;
        *(float2*)(og + (size_t)tr0 * OUTD + dc) =
            make_float2(oacc[nt][0] * inv0, oacc[nt][1] * inv0);
        *(float2*)(og + (size_t)(tr0 + 8) * OUTD + dc) =
            make_float2(oacc[nt][2] * inv1, oacc[nt][3] * inv1);
    }
}

// ================================================================================
// launch
// ================================================================================
extern "C" void kernel_launch(void* const* d_in, const int* in_sizes, int n_in,
                              void* d_out, int out_size)
{
    const float* src      = (const float*)d_in[0];
    const float* tgt      = (const float*)d_in[1];
    const float* src_mask = (const float*)d_in[2];
    const float* tgt_mask = (const float*)d_in[3];
    const float* Ws       = (const float*)d_in[4];
    const float* bs       = (const float*)d_in[5];
    const float* Wt       = (const float*)d_in[6];
    const float* bt       = (const float*)d_in[7];
    const float* Wo       = (const float*)d_in[8];
    const float* bo       = (const float*)d_in[9];
    float* out = (float*)d_out;

    float *kv, *q, *upd;
    cudaGetSymbolAddress((void**)&kv,  g_kv);
    cudaGetSymbolAddress((void**)&q,   g_q);
    cudaGetSymbolAddress((void**)&upd, g_upd);

    const int gemmSmem = 2 * 2 * 128 * 36 * 4;                                  // 73728
    const int attnSmem = (128 * 132 + 64 * 132 + 64 * 136 + 128 * 68 + 64) * 4; // 171264
    cudaFuncSetAttribute(gemm_tf32,   cudaFuncAttributeMaxDynamicSharedMemorySize, gemmSmem);
    cudaFuncSetAttribute(attn_kernel, cudaFuncAttributeMaxDynamicSharedMemorySize, attnSmem);

    dim3 blk(256);
    const int M = Bsz * NSEQ; // 8192

    // 1) src_trans = src @ Ws^T + bs, masked rows -> g_kv [8192, 2048]
    gemm_tf32<<<dim3(2048 / 128, M / 128), blk, gemmSmem>>>(
        src, 1024, Ws, 1024, bs, src_mask, kv, 2048, 1024, 0);

    // 2) tgt_trans = tgt @ Wt^T + bt, masked rows -> g_q [8192, 1024]
    gemm_tf32<<<dim3(1024 / 128, M / 128), blk, gemmSmem>>>(
        tgt, 1024, Wt, 1024, bt, tgt_mask, q, 1024, 1024, 0);

    // 3) flash attention -> g_upd [8192, 1024]
    attn_kernel<<<dim3(NSEQ / 128, Bsz * HH), blk, attnSmem>>>(q, kv, src_mask, upd);

    // 4) out = tgt @ Wo[:, :1024]^T + bo
    gemm_tf32<<<dim3(1024 / 128, M / 128), blk, gemmSmem>>>(
        tgt, 1024, Wo, 2048, bo, nullptr, out, 1024, 1024, 0);

    // 5) out += upd @ Wo[:, 1024:]^T
    gemm_tf32<<<dim3(1024 / 128, M / 128), blk, gemmSmem>>>(
        upd, 1024, Wo + 1024, 2048, nullptr, nullptr, out, 1024, 1024, 1);
}

// round 4
// speedup vs baseline: 1.2051x; 1.2051x over previous
#include <cuda_runtime.h>
#include <cstdint>

#define Bsz 8
#define NSEQ 1024
#define OUTD 1024
#define DHD 128

#define DINLINE __device__ __forceinline__

// ---------------- scratch (allocation-free rule: __device__ globals) ----------
__device__ __align__(16) float g_kv [8u*1024u*2048u];   // src_trans [B,NS,2*OUT]
__device__ __align__(16) float g_q  [8u*1024u*1024u];   // tgt_trans [B,NT,OUT]
__device__ __align__(16) float g_upd[8u*1024u*1024u];   // tgt_update [B,NT,OUT]
__device__ __align__(16) float r_src[8u*1024u*1024u];   // rna-rounded inputs
__device__ __align__(16) float r_tgt[8u*1024u*1024u];
__device__ __align__(16) float r_ws [2u*1024u*1024u];
__device__ __align__(16) float r_wt [1024u*1024u];
__device__ __align__(16) float r_wo [2u*1024u*1024u];

// ---------------- helpers ------------------------------------------------------
DINLINE uint32_t f2tf(float x) {
    uint32_t r;
    asm("cvt.rna.tf32.f32 %0, %1;" : "=r"(r) : "f"(x));
    return r;
}
DINLINE float f2tff(float x) { return __uint_as_float(f2tf(x)); }

DINLINE uint32_t smem_u32(const void* p) {
    uint32_t a;
    asm("{ .reg .u64 t; cvta.to.shared.u64 t, %1; cvt.u32.u64 %0, t; }" : "=r"(a) : "l"(p));
    return a;
}
DINLINE void cp16(uint32_t dst, const void* src) {
    asm volatile("cp.async.cg.shared.global [%0], [%1], 16;" :: "r"(dst), "l"(src) : "memory");
}
DINLINE void cp_commit() { asm volatile("cp.async.commit_group;" ::: "memory"); }
DINLINE void cp_wait0()  { asm volatile("cp.async.wait_group 0;" ::: "memory"); }
DINLINE void cp_wait1()  { asm volatile("cp.async.wait_group 1;" ::: "memory"); }

DINLINE void mma_tf32(float c[4], const uint32_t a[4], const uint32_t b[2]) {
    asm volatile(
        "mma.sync.aligned.m16n8k8.row.col.f32.tf32.tf32.f32 "
        "{%0,%1,%2,%3}, {%4,%5,%6,%7}, {%8,%9}, {%0,%1,%2,%3};"
        : "+f"(c[0]), "+f"(c[1]), "+f"(c[2]), "+f"(c[3])
        : "r"(a[0]), "r"(a[1]), "r"(a[2]), "r"(a[3]), "r"(b[0]), "r"(b[1]));
}

// ================================================================================
// rna rounding pre-pass
// ================================================================================
__global__ void round_tf32(const float4* __restrict__ in, float4* __restrict__ out, int n4)
{
    int i = blockIdx.x * blockDim.x + threadIdx.x;
    if (i < n4) {
        float4 v = in[i];
        v.x = f2tff(v.x); v.y = f2tff(v.y); v.z = f2tff(v.z); v.w = f2tff(v.w);
        out[i] = v;
    }
}

// ================================================================================
// GEMM: C[M,N] = Acat[M,K] @ W[N,K]^T (+bias) (*rowmask) (round?)
// Acat = [A0 | A1] virtual concat along K (each lda=1024; A1 used for kg>=1024).
// R1-proven compute layout: BM=BN=128, BK=32, 256 threads, 8 warps (2m x 4n),
// warp tile 64x32, acc[4][4][4], pad-36 smem, identical fragment mapping.
// Load path: cp.async.cg 3-stage pipeline on pre-rounded inputs.
// ================================================================================
#define GS 3
#define STGF (2 * 128 * 36)          // floats per stage (A then B)
#define STGB (STGF * 4)              // 36864 bytes

__global__ __launch_bounds__(256, 2)
void gemm_cp(const float* __restrict__ A0, const float* __restrict__ A1,
             const float* __restrict__ W, int ldw,
             const float* __restrict__ bias, const float* __restrict__ rowmask,
             float* __restrict__ C, int ldc, int nkb, int roundOut)
{
    extern __shared__ float smf[];
    const uint32_t sb = smem_u32(smf);

    const int tid  = threadIdx.x;
    const int lane = tid & 31;
    const int wid  = tid >> 5;
    const int wm   = wid & 1;     // 0..1
    const int wn   = wid >> 1;    // 0..3
    const int g    = lane >> 2;
    const int tg   = lane & 3;

    const int mBase = blockIdx.y * 128;
    const int nBase = blockIdx.x * 128;

    // cp.async offsets: 4 x 16B per operand per thread per k-block
    uint32_t dOf[4];
    int aOf[4], wOf[4];
#pragma unroll
    for (int i = 0; i < 4; i++) {
        int idx = tid + i * 256;
        int row = idx >> 3, c16 = idx & 7;       // 128 rows x 8 chunks
        dOf[i] = row * 144 + c16 * 16;           // pad-36 rows (144B)
        aOf[i] = (mBase + row) * 1024 + c16 * 4;
        wOf[i] = (nBase + row) * ldw + c16 * 4;
    }

    auto ISSUE = [&](int kb, int s) {
        const int kg = kb * 32;
        const float* Ap = (kg < 1024) ? A0 : A1;
        const int ka = kg & 1023;
        const uint32_t sa  = sb + s * STGB;
        const uint32_t sbb = sa + 128 * 144;
#pragma unroll
        for (int i = 0; i < 4; i++) cp16(sa  + dOf[i], Ap + aOf[i] + ka);
#pragma unroll
        for (int i = 0; i < 4; i++) cp16(sbb + dOf[i], W  + wOf[i] + kg);
        cp_commit();
    };

    float acc[4][4][4];
#pragma unroll
    for (int mt = 0; mt < 4; mt++)
#pragma unroll
        for (int nt = 0; nt < 4; nt++)
#pragma unroll
            for (int i = 0; i < 4; i++) acc[mt][nt][i] = 0.f;

    ISSUE(0, 0);
    ISSUE(1, 1);

    int s = 0;
    for (int kb = 0; kb < nkb; kb++) {
        if (kb + 1 < nkb) cp_wait1(); else cp_wait0();
        __syncthreads();

        const float* as = smf + s * STGF;
        const float* bs = as + 128 * 36;
#pragma unroll
        for (int ks = 0; ks < 4; ks++) {
            const int kc = ks * 8 + tg;
            uint32_t af[4][4], bf[4][2];
#pragma unroll
            for (int mt = 0; mt < 4; mt++) {
                int r = wm * 64 + mt * 16 + g;
                af[mt][0] = __float_as_uint(as[r * 36 + kc]);
                af[mt][1] = __float_as_uint(as[(r + 8) * 36 + kc]);
                af[mt][2] = __float_as_uint(as[r * 36 + kc + 4]);
                af[mt][3] = __float_as_uint(as[(r + 8) * 36 + kc + 4]);
            }
#pragma unroll
            for (int nt = 0; nt < 4; nt++) {
                int n = wn * 32 + nt * 8 + g;
                bf[nt][0] = __float_as_uint(bs[n * 36 + kc]);
                bf[nt][1] = __float_as_uint(bs[n * 36 + kc + 4]);
            }
#pragma unroll
            for (int mt = 0; mt < 4; mt++)
#pragma unroll
                for (int nt = 0; nt < 4; nt++)
                    mma_tf32(acc[mt][nt], af[mt], bf[nt]);
        }

        if (kb + 2 < nkb) ISSUE(kb + 2, (s + 2 >= GS) ? s - 1 : s + 2);
        s = (s + 1 == GS) ? 0 : s + 1;
    }

    // epilogue (R1's)
#pragma unroll
    for (int mt = 0; mt < 4; mt++) {
        int r0 = mBase + wm * 64 + mt * 16 + g;
        float mk0 = rowmask ? rowmask[r0]     : 1.f;
        float mk1 = rowmask ? rowmask[r0 + 8] : 1.f;
#pragma unroll
        for (int nt = 0; nt < 4; nt++) {
            int c = nBase + wn * 32 + nt * 8 + 2 * tg;
            float b0 = bias ? bias[c]     : 0.f;
            float b1 = bias ? bias[c + 1] : 0.f;
            float v00 = (acc[mt][nt][0] + b0) * mk0;
            float v01 = (acc[mt][nt][1] + b1) * mk0;
            float v10 = (acc[mt][nt][2] + b0) * mk1;
            float v11 = (acc[mt][nt][3] + b1) * mk1;
            if (roundOut) {
                v00 = f2tff(v00); v01 = f2tff(v01);
                v10 = f2tff(v10); v11 = f2tff(v11);
            }
            *(float2*)(C + (size_t)r0 * ldc + c)       = make_float2(v00, v01);
            *(float2*)(C + (size_t)(r0 + 8) * ldc + c) = make_float2(v10, v11);
        }
    }
}

// ================================================================================
// Flash attention — VERBATIM R1 (proven correct).
// ================================================================================
__global__ __launch_bounds__(256)
void attn_kernel(const float* __restrict__ Q, const float* __restrict__ KV,
                 const float* __restrict__ smask, float* __restrict__ O)
{
    extern __shared__ float sm[];
    float* q_s = sm;                   // [128][132]
    float* k_s = q_s + 128 * 132;      // [64][132]
    float* v_s = k_s + 64 * 132;       // [64][136]
    float* p_s = v_s + 64 * 136;       // [128][68]
    float* msk = p_s + 128 * 68;       // [64]

    const int tid  = threadIdx.x;
    const int lane = tid & 31;
    const int w    = tid >> 5;
    const int g    = lane >> 2;
    const int tg   = lane & 3;

    const int bh = blockIdx.y;
    const int b  = bh >> 3;
    const int h  = bh & 7;
    const int t0 = blockIdx.x * 128;

    const float* qg = Q + ((size_t)b * NSEQ + t0) * OUTD + h * DHD;
    const float* kg = KV + (size_t)b * NSEQ * (2 * OUTD) + h * DHD;
    const float* vg = kg + OUTD;

#pragma unroll
    for (int i = 0; i < 16; i++) {
        int idx = tid + i * 256;
        int row = idx >> 5, c4 = idx & 31;
        float4 v = *(const float4*)(qg + (size_t)row * OUTD + c4 * 4);
        v.x = f2tff(v.x); v.y = f2tff(v.y); v.z = f2tff(v.z); v.w = f2tff(v.w);
        *(float4*)(q_s + row * 132 + c4 * 4) = v;
    }

    float oacc[16][4];
#pragma unroll
    for (int nt = 0; nt < 16; nt++)
#pragma unroll
        for (int i = 0; i < 4; i++) oacc[nt][i] = 0.f;
    float m0 = -1e30f, m1 = -1e30f, l0 = 0.f, l1 = 0.f;

    const float sc = 0.0883883476483184405f; // 1/sqrt(128)

    for (int j = 0; j < NSEQ / 64; j++) {
        __syncthreads();
#pragma unroll
        for (int i = 0; i < 8; i++) {
            int idx = tid + i * 256;
            int row = idx >> 5, c4 = idx & 31;
            size_t go = (size_t)(j * 64 + row) * (2 * OUTD) + c4 * 4;
            float4 kk = *(const float4*)(kg + go);
            float4 vv = *(const float4*)(vg + go);
            kk.x = f2tff(kk.x); kk.y = f2tff(kk.y); kk.z = f2tff(kk.z); kk.w = f2tff(kk.w);
            vv.x = f2tff(vv.x); vv.y = f2tff(vv.y); vv.z = f2tff(vv.z); vv.w = f2tff(vv.w);
            *(float4*)(k_s + row * 132 + c4 * 4) = kk;
            *(float4*)(v_s + row * 136 + c4 * 4) = vv;
        }
        if (tid < 64) msk[tid] = smask[(size_t)b * NSEQ + j * 64 + tid];
        __syncthreads();

        float sacc[8][4];
#pragma unroll
        for (int nt = 0; nt < 8; nt++)
#pragma unroll
            for (int i = 0; i < 4; i++) sacc[nt][i] = 0.f;

#pragma unroll
        for (int ks = 0; ks < 16; ks++) {
            const int kc = ks * 8 + tg;
            const int r = w * 16 + g;
            uint32_t a[4];
            a[0] = __float_as_uint(q_s[r * 132 + kc]);
            a[1] = __float_as_uint(q_s[(r + 8) * 132 + kc]);
            a[2] = __float_as_uint(q_s[r * 132 + kc + 4]);
            a[3] = __float_as_uint(q_s[(r + 8) * 132 + kc + 4]);
#pragma unroll
            for (int nt = 0; nt < 8; nt++) {
                int srow = nt * 8 + g;
                uint32_t bb[2];
                bb[0] = __float_as_uint(k_s[srow * 132 + kc]);
                bb[1] = __float_as_uint(k_s[srow * 132 + kc + 4]);
                mma_tf32(sacc[nt], a, bb);
            }
        }

        float rmax0 = -1e30f, rmax1 = -1e30f;
#pragma unroll
        for (int nt = 0; nt < 8; nt++) {
#pragma unroll
            for (int i = 0; i < 4; i++) {
                float s = sacc[nt][i] * sc;
                int col = nt * 8 + 2 * tg + (i & 1);
                if (msk[col] == 0.f) s = -1e30f;
                sacc[nt][i] = s;
                if (i < 2) rmax0 = fmaxf(rmax0, s);
                else       rmax1 = fmaxf(rmax1, s);
            }
        }
        rmax0 = fmaxf(rmax0, __shfl_xor_sync(0xffffffffu, rmax0, 1));
        rmax0 = fmaxf(rmax0, __shfl_xor_sync(0xffffffffu, rmax0, 2));
        rmax1 = fmaxf(rmax1, __shfl_xor_sync(0xffffffffu, rmax1, 1));
        rmax1 = fmaxf(rmax1, __shfl_xor_sync(0xffffffffu, rmax1, 2));

        float mn0 = fmaxf(m0, rmax0), mn1 = fmaxf(m1, rmax1);
        float cf0 = __expf(m0 - mn0), cf1 = __expf(m1 - mn1);
        m0 = mn0; m1 = mn1;

        float rs0 = 0.f, rs1 = 0.f;
        const int pr = w * 16 + g;
#pragma unroll
        for (int nt = 0; nt < 8; nt++) {
            float p0 = __expf(sacc[nt][0] - mn0);
            float p1 = __expf(sacc[nt][1] - mn0);
            float p2 = __expf(sacc[nt][2] - mn1);
            float p3 = __expf(sacc[nt][3] - mn1);
            rs0 += p0 + p1; rs1 += p2 + p3;
            int pc = nt * 8 + 2 * tg;
            *(float2*)(p_s + pr * 68 + pc)       = make_float2(f2tff(p0), f2tff(p1));
            *(float2*)(p_s + (pr + 8) * 68 + pc) = make_float2(f2tff(p2), f2tff(p3));
        }
        rs0 += __shfl_xor_sync(0xffffffffu, rs0, 1);
        rs0 += __shfl_xor_sync(0xffffffffu, rs0, 2);
        rs1 += __shfl_xor_sync(0xffffffffu, rs1, 1);
        rs1 += __shfl_xor_sync(0xffffffffu, rs1, 2);
        l0 = l0 * cf0 + rs0;
        l1 = l1 * cf1 + rs1;

#pragma unroll
        for (int nt = 0; nt < 16; nt++) {
            oacc[nt][0] *= cf0; oacc[nt][1] *= cf0;
            oacc[nt][2] *= cf1; oacc[nt][3] *= cf1;
        }
        __syncwarp();

#pragma unroll
        for (int ks = 0; ks < 8; ks++) {
            const int kc = ks * 8 + tg;
            uint32_t a[4];
            a[0] = __float_as_uint(p_s[pr * 68 + kc]);
            a[1] = __float_as_uint(p_s[(pr + 8) * 68 + kc]);
            a[2] = __float_as_uint(p_s[pr * 68 + kc + 4]);
            a[3] = __float_as_uint(p_s[(pr + 8) * 68 + kc + 4]);
            const int sr = ks * 8 + tg;
#pragma unroll
            for (int nt = 0; nt < 16; nt++) {
                int dc = nt * 8 + g;
                uint32_t bb[2];
                bb[0] = __float_as_uint(v_s[sr * 136 + dc]);
                bb[1] = __float_as_uint(v_s[(sr + 4) * 136 + dc]);
                mma_tf32(oacc[nt], a, bb);
            }
        }
    }

    float inv0 = 1.f / l0, inv1 = 1.f / l1;
    const int tr0 = t0 + w * 16 + g;
    float* og = O + (size_t)b * NSEQ * OUTD + h * DHD;
#pragma unroll
    for (int nt = 0; nt < 16; nt++) {
        int dc = nt * 8 + 2 * tg;
        *(float2*)(og + (size_t)tr0 * OUTD + dc) =
            make_float2(oacc[nt][0] * inv0, oacc[nt][1] * inv0);
        *(float2*)(og + (size_t)(tr0 + 8) * OUTD + dc) =
            make_float2(oacc[nt][2] * inv1, oacc[nt][3] * inv1);
    }
}

// ================================================================================
// launch
// ================================================================================
extern "C" void kernel_launch(void* const* d_in, const int* in_sizes, int n_in,
                              void* d_out, int out_size)
{
    const float* src      = (const float*)d_in[0];
    const float* tgt      = (const float*)d_in[1];
    const float* src_mask = (const float*)d_in[2];
    const float* tgt_mask = (const float*)d_in[3];
    const float* Ws       = (const float*)d_in[4];
    const float* bs       = (const float*)d_in[5];
    const float* Wt       = (const float*)d_in[6];
    const float* bt       = (const float*)d_in[7];
    const float* Wo       = (const float*)d_in[8];
    const float* bo       = (const float*)d_in[9];
    float* out = (float*)d_out;

    float *kv, *q, *upd, *rsrc, *rtgt, *rws, *rwt, *rwo;
    cudaGetSymbolAddress((void**)&kv,   g_kv);
    cudaGetSymbolAddress((void**)&q,    g_q);
    cudaGetSymbolAddress((void**)&upd,  g_upd);
    cudaGetSymbolAddress((void**)&rsrc, r_src);
    cudaGetSymbolAddress((void**)&rtgt, r_tgt);
    cudaGetSymbolAddress((void**)&rws,  r_ws);
    cudaGetSymbolAddress((void**)&rwt,  r_wt);
    cudaGetSymbolAddress((void**)&rwo,  r_wo);

    const int gSmem = GS * STGB;                                              // 110592
    const int aSmem = (128 * 132 + 64 * 132 + 64 * 136 + 128 * 68 + 64) * 4;  // 171264
    cudaFuncSetAttribute(gemm_cp,     cudaFuncAttributeMaxDynamicSharedMemorySize, gSmem);
    cudaFuncSetAttribute(attn_kernel, cudaFuncAttributeMaxDynamicSharedMemorySize, aSmem);

    // 0) rna pre-round of raw inputs
    round_tf32<<<(8*1024*1024/4 + 255) / 256, 256>>>((const float4*)src, (float4*)rsrc, 8*1024*1024/4);
    round_tf32<<<(8*1024*1024/4 + 255) / 256, 256>>>((const float4*)tgt, (float4*)rtgt, 8*1024*1024/4);
    round_tf32<<<(2*1024*1024/4 + 255) / 256, 256>>>((const float4*)Ws,  (float4*)rws,  2*1024*1024/4);
    round_tf32<<<(1024*1024/4   + 255) / 256, 256>>>((const float4*)Wt,  (float4*)rwt,  1024*1024/4);
    round_tf32<<<(2*1024*1024/4 + 255) / 256, 256>>>((const float4*)Wo,  (float4*)rwo,  2*1024*1024/4);

    const int M = Bsz * NSEQ; // 8192

    // 1) kv = src @ Ws^T + bs, *src_mask (rounded)   [8192, 2048]
    gemm_cp<<<dim3(2048 / 128, M / 128), 256, gSmem>>>(
        rsrc, rsrc, rws, 1024, bs, src_mask, kv, 2048, 32, 1);

    // 2) q = tgt @ Wt^T + bt, *tgt_mask (rounded)    [8192, 1024]
    gemm_cp<<<dim3(1024 / 128, M / 128), 256, gSmem>>>(
        rtgt, rtgt, rwt, 1024, bt, tgt_mask, q, 1024, 32, 1);

    // 3) flash attention -> upd                      [8192, 1024]
    attn_kernel<<<dim3(NSEQ / 128, Bsz * 8), 256, aSmem>>>(q, kv, src_mask, upd);

    // 4) out = [tgt | upd] @ Wo^T + bo  (fused K=2048)
    gemm_cp<<<dim3(1024 / 128, M / 128), 256, gSmem>>>(
        rtgt, upd, rwo, 2048, bo, nullptr, out, 1024, 64, 0);
}

// round 5
// speedup vs baseline: 1.2810x; 1.0630x over previous
#include <cuda_runtime.h>
#include <cstdint>

#define Bsz 8
#define NSEQ 1024
#define OUTD 1024
#define DHD 128

#define DINLINE __device__ __forceinline__

// ---------------- scratch (allocation-free rule: __device__ globals) ----------
__device__ __align__(16) float g_kv [8u*1024u*2048u];   // src_trans [B,NS,2*OUT]
__device__ __align__(16) float g_q  [8u*1024u*1024u];   // tgt_trans [B,NT,OUT]
__device__ __align__(16) float g_upd[8u*1024u*1024u];   // tgt_update [B,NT,OUT]
__device__ __align__(16) float r_src[8u*1024u*1024u];   // rna-rounded inputs
__device__ __align__(16) float r_tgt[8u*1024u*1024u];
__device__ __align__(16) float r_ws [2u*1024u*1024u];
__device__ __align__(16) float r_wt [1024u*1024u];
__device__ __align__(16) float r_wo [2u*1024u*1024u];

// ---------------- helpers ------------------------------------------------------
DINLINE uint32_t f2tf(float x) {
    uint32_t r;
    asm("cvt.rna.tf32.f32 %0, %1;" : "=r"(r) : "f"(x));
    return r;
}
DINLINE float f2tff(float x) { return __uint_as_float(f2tf(x)); }

DINLINE uint32_t smem_u32(const void* p) {
    uint32_t a;
    asm("{ .reg .u64 t; cvta.to.shared.u64 t, %1; cvt.u32.u64 %0, t; }" : "=r"(a) : "l"(p));
    return a;
}
DINLINE void cp16(uint32_t dst, const void* src) {
    asm volatile("cp.async.cg.shared.global [%0], [%1], 16;" :: "r"(dst), "l"(src) : "memory");
}
DINLINE void cp_commit() { asm volatile("cp.async.commit_group;" ::: "memory"); }
DINLINE void cp_wait0()  { asm volatile("cp.async.wait_group 0;" ::: "memory"); }
DINLINE void cp_wait1()  { asm volatile("cp.async.wait_group 1;" ::: "memory"); }

DINLINE void mma_tf32(float c[4], const uint32_t a[4], const uint32_t b[2]) {
    asm volatile(
        "mma.sync.aligned.m16n8k8.row.col.f32.tf32.tf32.f32 "
        "{%0,%1,%2,%3}, {%4,%5,%6,%7}, {%8,%9}, {%0,%1,%2,%3};"
        : "+f"(c[0]), "+f"(c[1]), "+f"(c[2]), "+f"(c[3])
        : "r"(a[0]), "r"(a[1]), "r"(a[2]), "r"(a[3]), "r"(b[0]), "r"(b[1]));
}

// ================================================================================
// rna rounding pre-pass
// ================================================================================
__global__ void round_tf32(const float4* __restrict__ in, float4* __restrict__ out, int n4)
{
    int i = blockIdx.x * blockDim.x + threadIdx.x;
    if (i < n4) {
        float4 v = in[i];
        v.x = f2tff(v.x); v.y = f2tff(v.y); v.z = f2tff(v.z); v.w = f2tff(v.w);
        out[i] = v;
    }
}

// ================================================================================
// GEMM — VERBATIM R4 (proven): R1 compute layout + cp.async 3-stage pipeline.
// C[M,N] = [A0|A1][M,K] @ W[N,K]^T (+bias) (*rowmask) (round?)
// ================================================================================
#define GS 3
#define STGF (2 * 128 * 36)
#define STGB (STGF * 4)

__global__ __launch_bounds__(256, 2)
void gemm_cp(const float* __restrict__ A0, const float* __restrict__ A1,
             const float* __restrict__ W, int ldw,
             const float* __restrict__ bias, const float* __restrict__ rowmask,
             float* __restrict__ C, int ldc, int nkb, int roundOut)
{
    extern __shared__ float smf[];
    const uint32_t sb = smem_u32(smf);

    const int tid  = threadIdx.x;
    const int lane = tid & 31;
    const int wid  = tid >> 5;
    const int wm   = wid & 1;
    const int wn   = wid >> 1;
    const int g    = lane >> 2;
    const int tg   = lane & 3;

    const int mBase = blockIdx.y * 128;
    const int nBase = blockIdx.x * 128;

    uint32_t dOf[4];
    int aOf[4], wOf[4];
#pragma unroll
    for (int i = 0; i < 4; i++) {
        int idx = tid + i * 256;
        int row = idx >> 3, c16 = idx & 7;
        dOf[i] = row * 144 + c16 * 16;
        aOf[i] = (mBase + row) * 1024 + c16 * 4;
        wOf[i] = (nBase + row) * ldw + c16 * 4;
    }

    auto ISSUE = [&](int kb, int s) {
        const int kg = kb * 32;
        const float* Ap = (kg < 1024) ? A0 : A1;
        const int ka = kg & 1023;
        const uint32_t sa  = sb + s * STGB;
        const uint32_t sbb = sa + 128 * 144;
#pragma unroll
        for (int i = 0; i < 4; i++) cp16(sa  + dOf[i], Ap + aOf[i] + ka);
#pragma unroll
        for (int i = 0; i < 4; i++) cp16(sbb + dOf[i], W  + wOf[i] + kg);
        cp_commit();
    };

    float acc[4][4][4];
#pragma unroll
    for (int mt = 0; mt < 4; mt++)
#pragma unroll
        for (int nt = 0; nt < 4; nt++)
#pragma unroll
            for (int i = 0; i < 4; i++) acc[mt][nt][i] = 0.f;

    ISSUE(0, 0);
    ISSUE(1, 1);

    int s = 0;
    for (int kb = 0; kb < nkb; kb++) {
        if (kb + 1 < nkb) cp_wait1(); else cp_wait0();
        __syncthreads();

        const float* as = smf + s * STGF;
        const float* bs = as + 128 * 36;
#pragma unroll
        for (int ks = 0; ks < 4; ks++) {
            const int kc = ks * 8 + tg;
            uint32_t af[4][4], bf[4][2];
#pragma unroll
            for (int mt = 0; mt < 4; mt++) {
                int r = wm * 64 + mt * 16 + g;
                af[mt][0] = __float_as_uint(as[r * 36 + kc]);
                af[mt][1] = __float_as_uint(as[(r + 8) * 36 + kc]);
                af[mt][2] = __float_as_uint(as[r * 36 + kc + 4]);
                af[mt][3] = __float_as_uint(as[(r + 8) * 36 + kc + 4]);
            }
#pragma unroll
            for (int nt = 0; nt < 4; nt++) {
                int n = wn * 32 + nt * 8 + g;
                bf[nt][0] = __float_as_uint(bs[n * 36 + kc]);
                bf[nt][1] = __float_as_uint(bs[n * 36 + kc + 4]);
            }
#pragma unroll
            for (int mt = 0; mt < 4; mt++)
#pragma unroll
                for (int nt = 0; nt < 4; nt++)
                    mma_tf32(acc[mt][nt], af[mt], bf[nt]);
        }

        if (kb + 2 < nkb) ISSUE(kb + 2, (s + 2 >= GS) ? s - 1 : s + 2);
        s = (s + 1 == GS) ? 0 : s + 1;
    }

#pragma unroll
    for (int mt = 0; mt < 4; mt++) {
        int r0 = mBase + wm * 64 + mt * 16 + g;
        float mk0 = rowmask ? rowmask[r0]     : 1.f;
        float mk1 = rowmask ? rowmask[r0 + 8] : 1.f;
#pragma unroll
        for (int nt = 0; nt < 4; nt++) {
            int c = nBase + wn * 32 + nt * 8 + 2 * tg;
            float b0 = bias ? bias[c]     : 0.f;
            float b1 = bias ? bias[c + 1] : 0.f;
            float v00 = (acc[mt][nt][0] + b0) * mk0;
            float v01 = (acc[mt][nt][1] + b1) * mk0;
            float v10 = (acc[mt][nt][2] + b0) * mk1;
            float v11 = (acc[mt][nt][3] + b1) * mk1;
            if (roundOut) {
                v00 = f2tff(v00); v01 = f2tff(v01);
                v10 = f2tff(v10); v11 = f2tff(v11);
            }
            *(float2*)(C + (size_t)r0 * ldc + c)       = make_float2(v00, v01);
            *(float2*)(C + (size_t)(r0 + 8) * ldc + c) = make_float2(v10, v11);
        }
    }
}

// ================================================================================
// Flash attention v2: Q frags in registers, K/V/mask double-buffered via cp.async.
// All inputs (q, kv) are already tf32-rounded by the producing GEMM epilogues.
// smem: K[2][64][132] (aliases 128x132 Q staging), V[2][64][136],
//       P[128][68], mask[2][64].
// ================================================================================
#define KST (64 * 132)
#define VST (64 * 136)
#define VOFF (2 * KST)
#define POFF (VOFF + 2 * VST)
#define MOFF (POFF + 128 * 68)
#define ATTN_SMEMF (MOFF + 2 * 64)

__global__ __launch_bounds__(256)
void attn_kernel(const float* __restrict__ Q, const float* __restrict__ KV,
                 const float* __restrict__ smask, float* __restrict__ O)
{
    extern __shared__ float smf[];
    const uint32_t sb = smem_u32(smf);

    const int tid  = threadIdx.x;
    const int lane = tid & 31;
    const int w    = tid >> 5;
    const int g    = lane >> 2;
    const int tg   = lane & 3;

    const int bh = blockIdx.y;
    const int b  = bh >> 3;
    const int h  = bh & 7;
    const int t0 = blockIdx.x * 128;

    const float* qg = Q + ((size_t)b * NSEQ + t0) * OUTD + h * DHD;
    const float* kg = KV + (size_t)b * NSEQ * (2 * OUTD) + h * DHD;
    const float* vg = kg + OUTD;
    const float* mg = smask + (size_t)b * NSEQ;

    // ---- stage Q into smem (aliases the K double-buffer region) ----
#pragma unroll
    for (int i = 0; i < 16; i++) {
        int idx = tid + i * 256;
        int row = idx >> 5, c4 = idx & 31;
        *(float4*)(smf + row * 132 + c4 * 4) =
            *(const float4*)(qg + (size_t)row * OUTD + c4 * 4);
    }
    __syncthreads();

    // ---- cache this warp's Q fragments in registers ----
    uint32_t qf[16][4];
    {
        const int r = w * 16 + g;
#pragma unroll
        for (int ks = 0; ks < 16; ks++) {
            const int kc = ks * 8 + tg;
            qf[ks][0] = __float_as_uint(smf[r * 132 + kc]);
            qf[ks][1] = __float_as_uint(smf[(r + 8) * 132 + kc]);
            qf[ks][2] = __float_as_uint(smf[r * 132 + kc + 4]);
            qf[ks][3] = __float_as_uint(smf[(r + 8) * 132 + kc + 4]);
        }
    }
    __syncthreads();

    // ---- cp.async loader: 64 rows x 32 chunks(16B) per operand per buffer ----
    auto ISSUE = [&](int j) {
        const int st = j & 1;
#pragma unroll
        for (int i = 0; i < 8; i++) {
            int idx = tid + i * 256;
            int row = idx >> 5, c16 = idx & 31;   // FIXED vs R3 (was >>3 / &7)
            size_t go = (size_t)(j * 64 + row) * (2 * OUTD) + c16 * 4;
            cp16(sb + (st * KST + row * 132 + c16 * 4) * 4, kg + go);
            cp16(sb + (VOFF + st * VST + row * 136 + c16 * 4) * 4, vg + go);
        }
        if (tid < 16)
            cp16(sb + (MOFF + st * 64 + tid * 4) * 4, mg + j * 64 + tid * 4);
        cp_commit();
    };

    float oacc[16][4];
#pragma unroll
    for (int nt = 0; nt < 16; nt++)
#pragma unroll
        for (int i = 0; i < 4; i++) oacc[nt][i] = 0.f;
    float m0 = -1e30f, m1 = -1e30f, l0 = 0.f, l1 = 0.f;

    const float sc = 0.0883883476483184405f; // 1/sqrt(128)
    float* p_s = smf + POFF;
    const int pr = w * 16 + g;

    ISSUE(0);

    for (int j = 0; j < NSEQ / 64; j++) {
        const int st = j & 1;
        cp_wait0();
        __syncthreads();
        if (j + 1 < NSEQ / 64) ISSUE(j + 1);

        const float* k_s = smf + st * KST;
        const float* v_s = smf + VOFF + st * VST;
        const float* msk = smf + MOFF + st * 64;

        // S = Q @ K^T
        float sacc[8][4];
#pragma unroll
        for (int nt = 0; nt < 8; nt++)
#pragma unroll
            for (int i = 0; i < 4; i++) sacc[nt][i] = 0.f;

#pragma unroll
        for (int ks = 0; ks < 16; ks++) {
            const int kc = ks * 8 + tg;
#pragma unroll
            for (int nt = 0; nt < 8; nt++) {
                int srow = nt * 8 + g;
                uint32_t bb[2];
                bb[0] = __float_as_uint(k_s[srow * 132 + kc]);
                bb[1] = __float_as_uint(k_s[srow * 132 + kc + 4]);
                mma_tf32(sacc[nt], qf[ks], bb);
            }
        }

        // scale + mask + row max
        float rmax0 = -1e30f, rmax1 = -1e30f;
#pragma unroll
        for (int nt = 0; nt < 8; nt++) {
#pragma unroll
            for (int i = 0; i < 4; i++) {
                float sv = sacc[nt][i] * sc;
                int col = nt * 8 + 2 * tg + (i & 1);
                if (msk[col] == 0.f) sv = -1e30f;
                sacc[nt][i] = sv;
                if (i < 2) rmax0 = fmaxf(rmax0, sv);
                else       rmax1 = fmaxf(rmax1, sv);
            }
        }
        rmax0 = fmaxf(rmax0, __shfl_xor_sync(0xffffffffu, rmax0, 1));
        rmax0 = fmaxf(rmax0, __shfl_xor_sync(0xffffffffu, rmax0, 2));
        rmax1 = fmaxf(rmax1, __shfl_xor_sync(0xffffffffu, rmax1, 1));
        rmax1 = fmaxf(rmax1, __shfl_xor_sync(0xffffffffu, rmax1, 2));

        float mn0 = fmaxf(m0, rmax0), mn1 = fmaxf(m1, rmax1);
        float cf0 = __expf(m0 - mn0), cf1 = __expf(m1 - mn1);
        m0 = mn0; m1 = mn1;

        float rs0 = 0.f, rs1 = 0.f;
#pragma unroll
        for (int nt = 0; nt < 8; nt++) {
            float p0 = __expf(sacc[nt][0] - mn0);
            float p1 = __expf(sacc[nt][1] - mn0);
            float p2 = __expf(sacc[nt][2] - mn1);
            float p3 = __expf(sacc[nt][3] - mn1);
            rs0 += p0 + p1; rs1 += p2 + p3;
            int pc = nt * 8 + 2 * tg;
            *(float2*)(p_s + pr * 68 + pc)       = make_float2(f2tff(p0), f2tff(p1));
            *(float2*)(p_s + (pr + 8) * 68 + pc) = make_float2(f2tff(p2), f2tff(p3));
        }
        rs0 += __shfl_xor_sync(0xffffffffu, rs0, 1);
        rs0 += __shfl_xor_sync(0xffffffffu, rs0, 2);
        rs1 += __shfl_xor_sync(0xffffffffu, rs1, 1);
        rs1 += __shfl_xor_sync(0xffffffffu, rs1, 2);
        l0 = l0 * cf0 + rs0;
        l1 = l1 * cf1 + rs1;

#pragma unroll
        for (int nt = 0; nt < 16; nt++) {
            oacc[nt][0] *= cf0; oacc[nt][1] *= cf0;
            oacc[nt][2] *= cf1; oacc[nt][3] *= cf1;
        }
        __syncwarp();

        // O += P @ V
#pragma unroll
        for (int ks = 0; ks < 8; ks++) {
            const int kc = ks * 8 + tg;
            uint32_t a[4];
            a[0] = __float_as_uint(p_s[pr * 68 + kc]);
            a[1] = __float_as_uint(p_s[(pr + 8) * 68 + kc]);
            a[2] = __float_as_uint(p_s[pr * 68 + kc + 4]);
            a[3] = __float_as_uint(p_s[(pr + 8) * 68 + kc + 4]);
            const int sr = ks * 8 + tg;
#pragma unroll
            for (int nt = 0; nt < 16; nt++) {
                int dc = nt * 8 + g;
                uint32_t bb[2];
                bb[0] = __float_as_uint(v_s[sr * 136 + dc]);
                bb[1] = __float_as_uint(v_s[(sr + 4) * 136 + dc]);
                mma_tf32(oacc[nt], a, bb);
            }
        }
    }

    // write out (tf32-rounded: feeds the fused out-GEMM's cp.async A path)
    float inv0 = 1.f / l0, inv1 = 1.f / l1;
    const int tr0 = t0 + w * 16 + g;
    float* og = O + (size_t)b * NSEQ * OUTD + h * DHD;
#pragma unroll
    for (int nt = 0; nt < 16; nt++) {
        int dc = nt * 8 + 2 * tg;
        *(float2*)(og + (size_t)tr0 * OUTD + dc) =
            make_float2(f2tff(oacc[nt][0] * inv0), f2tff(oacc[nt][1] * inv0));
        *(float2*)(og + (size_t)(tr0 + 8) * OUTD + dc) =
            make_float2(f2tff(oacc[nt][2] * inv1), f2tff(oacc[nt][3] * inv1));
    }
}

// ================================================================================
// launch
// ================================================================================
extern "C" void kernel_launch(void* const* d_in, const int* in_sizes, int n_in,
                              void* d_out, int out_size)
{
    const float* src      = (const float*)d_in[0];
    const float* tgt      = (const float*)d_in[1];
    const float* src_mask = (const float*)d_in[2];
    const float* tgt_mask = (const float*)d_in[3];
    const float* Ws       = (const float*)d_in[4];
    const float* bs       = (const float*)d_in[5];
    const float* Wt       = (const float*)d_in[6];
    const float* bt       = (const float*)d_in[7];
    const float* Wo       = (const float*)d_in[8];
    const float* bo       = (const float*)d_in[9];
    float* out = (float*)d_out;

    float *kv, *q, *upd, *rsrc, *rtgt, *rws, *rwt, *rwo;
    cudaGetSymbolAddress((void**)&kv,   g_kv);
    cudaGetSymbolAddress((void**)&q,    g_q);
    cudaGetSymbolAddress((void**)&upd,  g_upd);
    cudaGetSymbolAddress((void**)&rsrc, r_src);
    cudaGetSymbolAddress((void**)&rtgt, r_tgt);
    cudaGetSymbolAddress((void**)&rws,  r_ws);
    cudaGetSymbolAddress((void**)&rwt,  r_wt);
    cudaGetSymbolAddress((void**)&rwo,  r_wo);

    const int gSmem = GS * STGB;               // 110592
    const int aSmem = ATTN_SMEMF * 4;          // 172544
    cudaFuncSetAttribute(gemm_cp,     cudaFuncAttributeMaxDynamicSharedMemorySize, gSmem);
    cudaFuncSetAttribute(attn_kernel, cudaFuncAttributeMaxDynamicSharedMemorySize, aSmem);

    // 0) rna pre-round of raw inputs
    round_tf32<<<(8*1024*1024/4 + 255) / 256, 256>>>((const float4*)src, (float4*)rsrc, 8*1024*1024/4);
    round_tf32<<<(8*1024*1024/4 + 255) / 256, 256>>>((const float4*)tgt, (float4*)rtgt, 8*1024*1024/4);
    round_tf32<<<(2*1024*1024/4 + 255) / 256, 256>>>((const float4*)Ws,  (float4*)rws,  2*1024*1024/4);
    round_tf32<<<(1024*1024/4   + 255) / 256, 256>>>((const float4*)Wt,  (float4*)rwt,  1024*1024/4);
    round_tf32<<<(2*1024*1024/4 + 255) / 256, 256>>>((const float4*)Wo,  (float4*)rwo,  2*1024*1024/4);

    const int M = Bsz * NSEQ; // 8192

    // 1) kv = src @ Ws^T + bs, *src_mask (rounded)   [8192, 2048]
    gemm_cp<<<dim3(2048 / 128, M / 128), 256, gSmem>>>(
        rsrc, rsrc, rws, 1024, bs, src_mask, kv, 2048, 32, 1);

    // 2) q = tgt @ Wt^T + bt, *tgt_mask (rounded)    [8192, 1024]
    gemm_cp<<<dim3(1024 / 128, M / 128), 256, gSmem>>>(
        rtgt, rtgt, rwt, 1024, bt, tgt_mask, q, 1024, 32, 1);

    // 3) flash attention -> upd (rounded)            [8192, 1024]
    attn_kernel<<<dim3(NSEQ / 128, Bsz * 8), 256, aSmem>>>(q, kv, src_mask, upd);

    // 4) out = [tgt | upd] @ Wo^T + bo  (fused K=2048)
    gemm_cp<<<dim3(1024 / 128, M / 128), 256, gSmem>>>(
        rtgt, upd, rwo, 2048, bo, nullptr, out, 1024, 64, 0);
}

// round 6
// speedup vs baseline: 1.3221x; 1.0321x over previous
#include <cuda_runtime.h>
#include <cstdint>

#define Bsz 8
#define NSEQ 1024
#define OUTD 1024
#define DHD 128

#define DINLINE __device__ __forceinline__

// ---------------- scratch (allocation-free rule: __device__ globals) ----------
__device__ __align__(16) float g_kv [8u*1024u*2048u];   // src_trans [B,NS,2*OUT]
__device__ __align__(16) float g_q  [8u*1024u*1024u];   // tgt_trans [B,NT,OUT]
__device__ __align__(16) float g_upd[8u*1024u*1024u];   // tgt_update [B,NT,OUT]
__device__ __align__(16) float r_src[8u*1024u*1024u];   // rna-rounded inputs
__device__ __align__(16) float r_tgt[8u*1024u*1024u];
__device__ __align__(16) float r_ws [2u*1024u*1024u];
__device__ __align__(16) float r_wt [1024u*1024u];
__device__ __align__(16) float r_wo [2u*1024u*1024u];

// ---------------- helpers ------------------------------------------------------
DINLINE uint32_t f2tf(float x) {
    uint32_t r;
    asm("cvt.rna.tf32.f32 %0, %1;" : "=r"(r) : "f"(x));
    return r;
}
DINLINE float f2tff(float x) { return __uint_as_float(f2tf(x)); }

DINLINE uint32_t smem_u32(const void* p) {
    uint32_t a;
    asm("{ .reg .u64 t; cvta.to.shared.u64 t, %1; cvt.u32.u64 %0, t; }" : "=r"(a) : "l"(p));
    return a;
}
DINLINE void cp16(uint32_t dst, const void* src) {
    asm volatile("cp.async.cg.shared.global [%0], [%1], 16;" :: "r"(dst), "l"(src) : "memory");
}
DINLINE void cp_commit() { asm volatile("cp.async.commit_group;" ::: "memory"); }
DINLINE void cp_wait0()  { asm volatile("cp.async.wait_group 0;" ::: "memory"); }
DINLINE void cp_wait1()  { asm volatile("cp.async.wait_group 1;" ::: "memory"); }

DINLINE void mma_tf32(float c[4], const uint32_t a[4], const uint32_t b[2]) {
    asm volatile(
        "mma.sync.aligned.m16n8k8.row.col.f32.tf32.tf32.f32 "
        "{%0,%1,%2,%3}, {%4,%5,%6,%7}, {%8,%9}, {%0,%1,%2,%3};"
        : "+f"(c[0]), "+f"(c[1]), "+f"(c[2]), "+f"(c[3])
        : "r"(a[0]), "r"(a[1]), "r"(a[2]), "r"(a[3]), "r"(b[0]), "r"(b[1]));
}

// ================================================================================
// rna rounding pre-pass
// ================================================================================
__global__ void round_tf32(const float4* __restrict__ in, float4* __restrict__ out, int n4)
{
    int i = blockIdx.x * blockDim.x + threadIdx.x;
    if (i < n4) {
        float4 v = in[i];
        v.x = f2tff(v.x); v.y = f2tff(v.y); v.z = f2tff(v.z); v.w = f2tff(v.w);
        out[i] = v;
    }
}

// ================================================================================
// GEMM: C[M,N] = [A0|A1][M,K] @ W[N,K]^T (+bias) (*rowmask) (round?)
// BM=BN=128, BK=32. 128 threads, 4 warps (2m x 2n), warp tile 64x64.
// Fragment-LDS : mma ratio = 1.0 (vs 1.5 for the 8-warp 64x32 layout).
// cp.async.cg 3-stage pipeline, pad-36 smem, launch_bounds(128,2) -> 2 CTA/SM.
// ================================================================================
#define GS 3
#define STGF (2 * 128 * 36)
#define STGB (STGF * 4)

__global__ __launch_bounds__(128, 2)
void gemm_cp(const float* __restrict__ A0, const float* __restrict__ A1,
             const float* __restrict__ W, int ldw,
             const float* __restrict__ bias, const float* __restrict__ rowmask,
             float* __restrict__ C, int ldc, int nkb, int roundOut)
{
    extern __shared__ float smf[];
    const uint32_t sb = smem_u32(smf);

    const int tid  = threadIdx.x;
    const int lane = tid & 31;
    const int wid  = tid >> 5;
    const int wm   = wid & 1;     // 0..1 -> m offset 64*wm
    const int wn   = wid >> 1;    // 0..1 -> n offset 64*wn
    const int g    = lane >> 2;
    const int tg   = lane & 3;

    const int mBase = blockIdx.y * 128;
    const int nBase = blockIdx.x * 128;

    // cp.async offsets: 8 x 16B per operand per thread per k-block
    uint32_t dOf[8];
    int aOf[8], wOf[8];
#pragma unroll
    for (int i = 0; i < 8; i++) {
        int idx = tid + i * 128;
        int row = idx >> 3, c16 = idx & 7;       // 128 rows x 8 chunks (32 floats)
        dOf[i] = row * 144 + c16 * 16;           // pad-36 rows (144B)
        aOf[i] = (mBase + row) * 1024 + c16 * 4;
        wOf[i] = (nBase + row) * ldw + c16 * 4;
    }

    auto ISSUE = [&](int kb, int s) {
        const int kg = kb * 32;
        const float* Ap = (kg < 1024) ? A0 : A1;
        const int ka = kg & 1023;
        const uint32_t sa  = sb + s * STGB;
        const uint32_t sbb = sa + 128 * 144;
#pragma unroll
        for (int i = 0; i < 8; i++) cp16(sa  + dOf[i], Ap + aOf[i] + ka);
#pragma unroll
        for (int i = 0; i < 8; i++) cp16(sbb + dOf[i], W  + wOf[i] + kg);
        cp_commit();
    };

    float acc[4][8][4];
#pragma unroll
    for (int mt = 0; mt < 4; mt++)
#pragma unroll
        for (int nt = 0; nt < 8; nt++)
#pragma unroll
            for (int i = 0; i < 4; i++) acc[mt][nt][i] = 0.f;

    ISSUE(0, 0);
    ISSUE(1, 1);

    int s = 0;
    for (int kb = 0; kb < nkb; kb++) {
        if (kb + 1 < nkb) cp_wait1(); else cp_wait0();
        __syncthreads();

        const float* as = smf + s * STGF;
        const float* bs = as + 128 * 36;
#pragma unroll
        for (int ks = 0; ks < 4; ks++) {
            const int kc = ks * 8 + tg;
            uint32_t af[4][4], bf[8][2];
#pragma unroll
            for (int mt = 0; mt < 4; mt++) {
                int r = wm * 64 + mt * 16 + g;
                af[mt][0] = __float_as_uint(as[r * 36 + kc]);
                af[mt][1] = __float_as_uint(as[(r + 8) * 36 + kc]);
                af[mt][2] = __float_as_uint(as[r * 36 + kc + 4]);
                af[mt][3] = __float_as_uint(as[(r + 8) * 36 + kc + 4]);
            }
#pragma unroll
            for (int nt = 0; nt < 8; nt++) {
                int n = wn * 64 + nt * 8 + g;
                bf[nt][0] = __float_as_uint(bs[n * 36 + kc]);
                bf[nt][1] = __float_as_uint(bs[n * 36 + kc + 4]);
            }
#pragma unroll
            for (int mt = 0; mt < 4; mt++)
#pragma unroll
                for (int nt = 0; nt < 8; nt++)
                    mma_tf32(acc[mt][nt], af[mt], bf[nt]);
        }

        if (kb + 2 < nkb) ISSUE(kb + 2, (s + 2 >= GS) ? s - 1 : s + 2);
        s = (s + 1 == GS) ? 0 : s + 1;
    }

    // epilogue
#pragma unroll
    for (int mt = 0; mt < 4; mt++) {
        int r0 = mBase + wm * 64 + mt * 16 + g;
        float mk0 = rowmask ? rowmask[r0]     : 1.f;
        float mk1 = rowmask ? rowmask[r0 + 8] : 1.f;
#pragma unroll
        for (int nt = 0; nt < 8; nt++) {
            int c = nBase + wn * 64 + nt * 8 + 2 * tg;
            float b0 = bias ? bias[c]     : 0.f;
            float b1 = bias ? bias[c + 1] : 0.f;
            float v00 = (acc[mt][nt][0] + b0) * mk0;
            float v01 = (acc[mt][nt][1] + b1) * mk0;
            float v10 = (acc[mt][nt][2] + b0) * mk1;
            float v11 = (acc[mt][nt][3] + b1) * mk1;
            if (roundOut) {
                v00 = f2tff(v00); v01 = f2tff(v01);
                v10 = f2tff(v10); v11 = f2tff(v11);
            }
            *(float2*)(C + (size_t)r0 * ldc + c)       = make_float2(v00, v01);
            *(float2*)(C + (size_t)(r0 + 8) * ldc + c) = make_float2(v10, v11);
        }
    }
}

// ================================================================================
// Flash attention — VERBATIM R5 (proven): reg-Q + cp.async double-buffered K/V.
// ================================================================================
#define KST (64 * 132)
#define VST (64 * 136)
#define VOFF (2 * KST)
#define POFF (VOFF + 2 * VST)
#define MOFF (POFF + 128 * 68)
#define ATTN_SMEMF (MOFF + 2 * 64)

__global__ __launch_bounds__(256)
void attn_kernel(const float* __restrict__ Q, const float* __restrict__ KV,
                 const float* __restrict__ smask, float* __restrict__ O)
{
    extern __shared__ float smf[];
    const uint32_t sb = smem_u32(smf);

    const int tid  = threadIdx.x;
    const int lane = tid & 31;
    const int w    = tid >> 5;
    const int g    = lane >> 2;
    const int tg   = lane & 3;

    const int bh = blockIdx.y;
    const int b  = bh >> 3;
    const int h  = bh & 7;
    const int t0 = blockIdx.x * 128;

    const float* qg = Q + ((size_t)b * NSEQ + t0) * OUTD + h * DHD;
    const float* kg = KV + (size_t)b * NSEQ * (2 * OUTD) + h * DHD;
    const float* vg = kg + OUTD;
    const float* mg = smask + (size_t)b * NSEQ;

#pragma unroll
    for (int i = 0; i < 16; i++) {
        int idx = tid + i * 256;
        int row = idx >> 5, c4 = idx & 31;
        *(float4*)(smf + row * 132 + c4 * 4) =
            *(const float4*)(qg + (size_t)row * OUTD + c4 * 4);
    }
    __syncthreads();

    uint32_t qf[16][4];
    {
        const int r = w * 16 + g;
#pragma unroll
        for (int ks = 0; ks < 16; ks++) {
            const int kc = ks * 8 + tg;
            qf[ks][0] = __float_as_uint(smf[r * 132 + kc]);
            qf[ks][1] = __float_as_uint(smf[(r + 8) * 132 + kc]);
            qf[ks][2] = __float_as_uint(smf[r * 132 + kc + 4]);
            qf[ks][3] = __float_as_uint(smf[(r + 8) * 132 + kc + 4]);
        }
    }
    __syncthreads();

    auto ISSUE = [&](int j) {
        const int st = j & 1;
#pragma unroll
        for (int i = 0; i < 8; i++) {
            int idx = tid + i * 256;
            int row = idx >> 5, c16 = idx & 31;
            size_t go = (size_t)(j * 64 + row) * (2 * OUTD) + c16 * 4;
            cp16(sb + (st * KST + row * 132 + c16 * 4) * 4, kg + go);
            cp16(sb + (VOFF + st * VST + row * 136 + c16 * 4) * 4, vg + go);
        }
        if (tid < 16)
            cp16(sb + (MOFF + st * 64 + tid * 4) * 4, mg + j * 64 + tid * 4);
        cp_commit();
    };

    float oacc[16][4];
#pragma unroll
    for (int nt = 0; nt < 16; nt++)
#pragma unroll
        for (int i = 0; i < 4; i++) oacc[nt][i] = 0.f;
    float m0 = -1e30f, m1 = -1e30f, l0 = 0.f, l1 = 0.f;

    const float sc = 0.0883883476483184405f; // 1/sqrt(128)
    float* p_s = smf + POFF;
    const int pr = w * 16 + g;

    ISSUE(0);

    for (int j = 0; j < NSEQ / 64; j++) {
        const int st = j & 1;
        cp_wait0();
        __syncthreads();
        if (j + 1 < NSEQ / 64) ISSUE(j + 1);

        const float* k_s = smf + st * KST;
        const float* v_s = smf + VOFF + st * VST;
        const float* msk = smf + MOFF + st * 64;

        float sacc[8][4];
#pragma unroll
        for (int nt = 0; nt < 8; nt++)
#pragma unroll
            for (int i = 0; i < 4; i++) sacc[nt][i] = 0.f;

#pragma unroll
        for (int ks = 0; ks < 16; ks++) {
            const int kc = ks * 8 + tg;
#pragma unroll
            for (int nt = 0; nt < 8; nt++) {
                int srow = nt * 8 + g;
                uint32_t bb[2];
                bb[0] = __float_as_uint(k_s[srow * 132 + kc]);
                bb[1] = __float_as_uint(k_s[srow * 132 + kc + 4]);
                mma_tf32(sacc[nt], qf[ks], bb);
            }
        }

        float rmax0 = -1e30f, rmax1 = -1e30f;
#pragma unroll
        for (int nt = 0; nt < 8; nt++) {
#pragma unroll
            for (int i = 0; i < 4; i++) {
                float sv = sacc[nt][i] * sc;
                int col = nt * 8 + 2 * tg + (i & 1);
                if (msk[col] == 0.f) sv = -1e30f;
                sacc[nt][i] = sv;
                if (i < 2) rmax0 = fmaxf(rmax0, sv);
                else       rmax1 = fmaxf(rmax1, sv);
            }
        }
        rmax0 = fmaxf(rmax0, __shfl_xor_sync(0xffffffffu, rmax0, 1));
        rmax0 = fmaxf(rmax0, __shfl_xor_sync(0xffffffffu, rmax0, 2));
        rmax1 = fmaxf(rmax1, __shfl_xor_sync(0xffffffffu, rmax1, 1));
        rmax1 = fmaxf(rmax1, __shfl_xor_sync(0xffffffffu, rmax1, 2));

        float mn0 = fmaxf(m0, rmax0), mn1 = fmaxf(m1, rmax1);
        float cf0 = __expf(m0 - mn0), cf1 = __expf(m1 - mn1);
        m0 = mn0; m1 = mn1;

        float rs0 = 0.f, rs1 = 0.f;
#pragma unroll
        for (int nt = 0; nt < 8; nt++) {
            float p0 = __expf(sacc[nt][0] - mn0);
            float p1 = __expf(sacc[nt][1] - mn0);
            float p2 = __expf(sacc[nt][2] - mn1);
            float p3 = __expf(sacc[nt][3] - mn1);
            rs0 += p0 + p1; rs1 += p2 + p3;
            int pc = nt * 8 + 2 * tg;
            *(float2*)(p_s + pr * 68 + pc)       = make_float2(f2tff(p0), f2tff(p1));
            *(float2*)(p_s + (pr + 8) * 68 + pc) = make_float2(f2tff(p2), f2tff(p3));
        }
        rs0 += __shfl_xor_sync(0xffffffffu, rs0, 1);
        rs0 += __shfl_xor_sync(0xffffffffu, rs0, 2);
        rs1 += __shfl_xor_sync(0xffffffffu, rs1, 1);
        rs1 += __shfl_xor_sync(0xffffffffu, rs1, 2);
        l0 = l0 * cf0 + rs0;
        l1 = l1 * cf1 + rs1;

#pragma unroll
        for (int nt = 0; nt < 16; nt++) {
            oacc[nt][0] *= cf0; oacc[nt][1] *= cf0;
            oacc[nt][2] *= cf1; oacc[nt][3] *= cf1;
        }
        __syncwarp();

#pragma unroll
        for (int ks = 0; ks < 8; ks++) {
            const int kc = ks * 8 + tg;
            uint32_t a[4];
            a[0] = __float_as_uint(p_s[pr * 68 + kc]);
            a[1] = __float_as_uint(p_s[(pr + 8) * 68 + kc]);
            a[2] = __float_as_uint(p_s[pr * 68 + kc + 4]);
            a[3] = __float_as_uint(p_s[(pr + 8) * 68 + kc + 4]);
            const int sr = ks * 8 + tg;
#pragma unroll
            for (int nt = 0; nt < 16; nt++) {
                int dc = nt * 8 + g;
                uint32_t bb[2];
                bb[0] = __float_as_uint(v_s[sr * 136 + dc]);
                bb[1] = __float_as_uint(v_s[(sr + 4) * 136 + dc]);
                mma_tf32(oacc[nt], a, bb);
            }
        }
    }

    float inv0 = 1.f / l0, inv1 = 1.f / l1;
    const int tr0 = t0 + w * 16 + g;
    float* og = O + (size_t)b * NSEQ * OUTD + h * DHD;
#pragma unroll
    for (int nt = 0; nt < 16; nt++) {
        int dc = nt * 8 + 2 * tg;
        *(float2*)(og + (size_t)tr0 * OUTD + dc) =
            make_float2(f2tff(oacc[nt][0] * inv0), f2tff(oacc[nt][1] * inv0));
        *(float2*)(og + (size_t)(tr0 + 8) * OUTD + dc) =
            make_float2(f2tff(oacc[nt][2] * inv1), f2tff(oacc[nt][3] * inv1));
    }
}

// ================================================================================
// launch
// ================================================================================
extern "C" void kernel_launch(void* const* d_in, const int* in_sizes, int n_in,
                              void* d_out, int out_size)
{
    const float* src      = (const float*)d_in[0];
    const float* tgt      = (const float*)d_in[1];
    const float* src_mask = (const float*)d_in[2];
    const float* tgt_mask = (const float*)d_in[3];
    const float* Ws       = (const float*)d_in[4];
    const float* bs       = (const float*)d_in[5];
    const float* Wt       = (const float*)d_in[6];
    const float* bt       = (const float*)d_in[7];
    const float* Wo       = (const float*)d_in[8];
    const float* bo       = (const float*)d_in[9];
    float* out = (float*)d_out;

    float *kv, *q, *upd, *rsrc, *rtgt, *rws, *rwt, *rwo;
    cudaGetSymbolAddress((void**)&kv,   g_kv);
    cudaGetSymbolAddress((void**)&q,    g_q);
    cudaGetSymbolAddress((void**)&upd,  g_upd);
    cudaGetSymbolAddress((void**)&rsrc, r_src);
    cudaGetSymbolAddress((void**)&rtgt, r_tgt);
    cudaGetSymbolAddress((void**)&rws,  r_ws);
    cudaGetSymbolAddress((void**)&rwt,  r_wt);
    cudaGetSymbolAddress((void**)&rwo,  r_wo);

    const int gSmem = GS * STGB;               // 110592
    const int aSmem = ATTN_SMEMF * 4;          // 172544
    cudaFuncSetAttribute(gemm_cp,     cudaFuncAttributeMaxDynamicSharedMemorySize, gSmem);
    cudaFuncSetAttribute(attn_kernel, cudaFuncAttributeMaxDynamicSharedMemorySize, aSmem);

    // 0) rna pre-round of raw inputs
    round_tf32<<<(8*1024*1024/4 + 255) / 256, 256>>>((const float4*)src, (float4*)rsrc, 8*1024*1024/4);
    round_tf32<<<(8*1024*1024/4 + 255) / 256, 256>>>((const float4*)tgt, (float4*)rtgt, 8*1024*1024/4);
    round_tf32<<<(2*1024*1024/4 + 255) / 256, 256>>>((const float4*)Ws,  (float4*)rws,  2*1024*1024/4);
    round_tf32<<<(1024*1024/4   + 255) / 256, 256>>>((const float4*)Wt,  (float4*)rwt,  1024*1024/4);
    round_tf32<<<(2*1024*1024/4 + 255) / 256, 256>>>((const float4*)Wo,  (float4*)rwo,  2*1024*1024/4);

    const int M = Bsz * NSEQ; // 8192

    // 1) kv = src @ Ws^T + bs, *src_mask (rounded)   [8192, 2048]
    gemm_cp<<<dim3(2048 / 128, M / 128), 128, gSmem>>>(
        rsrc, rsrc, rws, 1024, bs, src_mask, kv, 2048, 32, 1);

    // 2) q = tgt @ Wt^T + bt, *tgt_mask (rounded)    [8192, 1024]
    gemm_cp<<<dim3(1024 / 128, M / 128), 128, gSmem>>>(
        rtgt, rtgt, rwt, 1024, bt, tgt_mask, q, 1024, 32, 1);

    // 3) flash attention -> upd (rounded)            [8192, 1024]
    attn_kernel<<<dim3(NSEQ / 128, Bsz * 8), 256, aSmem>>>(q, kv, src_mask, upd);

    // 4) out = [tgt | upd] @ Wo^T + bo  (fused K=2048)
    gemm_cp<<<dim3(1024 / 128, M / 128), 128, gSmem>>>(
        rtgt, upd, rwo, 2048, bo, nullptr, out, 1024, 64, 0);
}

// round 7
// speedup vs baseline: 2.2871x; 1.7299x over previous
#include <cuda_runtime.h>
#include <cuda_fp16.h>
#include <cstdint>

#define Bsz 8
#define NSEQ 1024
#define OUTD 1024
#define DHD 128

#define DINLINE __device__ __forceinline__

// ---------------- scratch (allocation-free rule: __device__ globals) ----------
__device__ __align__(16) __half h_kv [8u*1024u*2048u];   // src_trans half [B*NS,2048]
__device__ __align__(16) __half h_q  [8u*1024u*1024u];   // tgt_trans half
__device__ __align__(16) __half h_upd[8u*1024u*1024u];   // tgt_update half
__device__ __align__(16) __half h_src[8u*1024u*1024u];   // fp16 inputs
__device__ __align__(16) __half h_tgt[8u*1024u*1024u];
__device__ __align__(16) __half h_ws [2u*1024u*1024u];
__device__ __align__(16) __half h_wt [1024u*1024u];
__device__ __align__(16) __half h_wo [2u*1024u*1024u];

// ---------------- helpers ------------------------------------------------------
DINLINE uint32_t smem_u32(const void* p) {
    uint32_t a;
    asm("{ .reg .u64 t; cvta.to.shared.u64 t, %1; cvt.u32.u64 %0, t; }" : "=r"(a) : "l"(p));
    return a;
}
DINLINE void cp16(uint32_t dst, const void* src) {
    asm volatile("cp.async.cg.shared.global [%0], [%1], 16;" :: "r"(dst), "l"(src) : "memory");
}
DINLINE void cp_commit() { asm volatile("cp.async.commit_group;" ::: "memory"); }
DINLINE void cp_wait0()  { asm volatile("cp.async.wait_group 0;" ::: "memory"); }
DINLINE void cp_wait1()  { asm volatile("cp.async.wait_group 1;" ::: "memory"); }

// fp16 mma: D[16x8] += A[16x16] * B[16x8], f32 accumulate.
// C-fragment layout identical to m16n8k8: c0/c1 row g cols 2tg/2tg+1, c2/c3 row g+8.
DINLINE void mma_h(float c[4], const uint32_t a[4], const uint32_t b[2]) {
    asm volatile(
        "mma.sync.aligned.m16n8k16.row.col.f32.f16.f16.f32 "
        "{%0,%1,%2,%3}, {%4,%5,%6,%7}, {%8,%9}, {%0,%1,%2,%3};"
        : "+f"(c[0]), "+f"(c[1]), "+f"(c[2]), "+f"(c[3])
        : "r"(a[0]), "r"(a[1]), "r"(a[2]), "r"(a[3]), "r"(b[0]), "r"(b[1]));
}

DINLINE void ldsm_x4_t(uint32_t& r0, uint32_t& r1, uint32_t& r2, uint32_t& r3, uint32_t a) {
    asm volatile("ldmatrix.sync.aligned.m8n8.x4.trans.shared.b16 {%0,%1,%2,%3}, [%4];"
                 : "=r"(r0), "=r"(r1), "=r"(r2), "=r"(r3) : "r"(a));
}

DINLINE uint32_t ldh2(const __half* p) { return *(const uint32_t*)p; }
DINLINE uint32_t packh2(float x, float y) {
    __half2 h = __floats2half2_rn(x, y);
    return *reinterpret_cast<uint32_t*>(&h);
}

// ================================================================================
// f32 -> fp16 conversion pre-pass (8 floats / thread)
// ================================================================================
__global__ void f2h(const float4* __restrict__ in, uint4* __restrict__ out, int n8)
{
    int i = blockIdx.x * blockDim.x + threadIdx.x;
    if (i < n8) {
        float4 a = in[2 * i], b = in[2 * i + 1];
        uint4 o;
        o.x = packh2(a.x, a.y);
        o.y = packh2(a.z, a.w);
        o.z = packh2(b.x, b.y);
        o.w = packh2(b.z, b.w);
        out[i] = o;
    }
}

// ================================================================================
// fp16 GEMM: C[M,N] = [A0|A1][M,K] @ W[N,K]^T (+bias f32) (*rowmask f32)
// BM=BN=128, BK=32 (2 x k16). 128 threads, 4 warps (2m x 2n), warp tile 64x64.
// cp.async 3-stage pipeline; smem rows padded to 40 halves (bank-conflict-free
// half2 fragment loads: bank = (20r + 8ks + tg) % 32, all distinct).
// Output: fp16 (outHalf=1) or f32.
// ================================================================================
#define GS 3
#define STGH (2 * 128 * 40)          // halves per stage (A then B)
#define STGB (STGH * 2)              // 20480 bytes

__global__ __launch_bounds__(128, 2)
void gemm_h(const __half* __restrict__ A0, const __half* __restrict__ A1,
            const __half* __restrict__ W, int ldw,
            const float* __restrict__ bias, const float* __restrict__ rowmask,
            void* __restrict__ Cv, int ldc, int nkb, int outHalf)
{
    extern __shared__ __half smh[];
    const uint32_t sb = smem_u32(smh);

    const int tid  = threadIdx.x;
    const int lane = tid & 31;
    const int wid  = tid >> 5;
    const int wm   = wid & 1;
    const int wn   = wid >> 1;
    const int g    = lane >> 2;
    const int tg   = lane & 3;

    const int mBase = blockIdx.y * 128;
    const int nBase = blockIdx.x * 128;

    // cp.async: tile = 128 rows x 32 halves = 512 x 16B chunks; 4 per thread/operand
    uint32_t dOf[4];
    int aOf[4], wOf[4];
#pragma unroll
    for (int i = 0; i < 4; i++) {
        int idx = tid + i * 128;
        int row = idx >> 2, c = idx & 3;          // 4 chunks of 8 halves per row
        dOf[i] = row * 80 + c * 16;               // pad-40 rows (80B)
        aOf[i] = (mBase + row) * 1024 + c * 8;    // halves
        wOf[i] = (nBase + row) * ldw + c * 8;
    }

    auto ISSUE = [&](int kb, int s) {
        const int kg = kb * 32;
        const __half* Ap = (kg < 1024) ? A0 : A1;
        const int ka = kg & 1023;
        const uint32_t sa  = sb + s * STGB;
        const uint32_t sbb = sa + 128 * 80;
#pragma unroll
        for (int i = 0; i < 4; i++) cp16(sa  + dOf[i], Ap + aOf[i] + ka);
#pragma unroll
        for (int i = 0; i < 4; i++) cp16(sbb + dOf[i], W  + wOf[i] + kg);
        cp_commit();
    };

    float acc[4][8][4];
#pragma unroll
    for (int mt = 0; mt < 4; mt++)
#pragma unroll
        for (int nt = 0; nt < 8; nt++)
#pragma unroll
            for (int i = 0; i < 4; i++) acc[mt][nt][i] = 0.f;

    ISSUE(0, 0);
    ISSUE(1, 1);

    int s = 0;
    for (int kb = 0; kb < nkb; kb++) {
        if (kb + 1 < nkb) cp_wait1(); else cp_wait0();
        __syncthreads();

        const __half* as = smh + s * STGH;
        const __half* bs = as + 128 * 40;
#pragma unroll
        for (int ks = 0; ks < 2; ks++) {
            const int kc = ks * 16 + 2 * tg;     // half index within 32-wide row
            uint32_t af[4][4], bf[8][2];
#pragma unroll
            for (int mt = 0; mt < 4; mt++) {
                int r = wm * 64 + mt * 16 + g;
                af[mt][0] = ldh2(as + r * 40 + kc);
                af[mt][1] = ldh2(as + (r + 8) * 40 + kc);
                af[mt][2] = ldh2(as + r * 40 + kc + 8);
                af[mt][3] = ldh2(as + (r + 8) * 40 + kc + 8);
            }
#pragma unroll
            for (int nt = 0; nt < 8; nt++) {
                int n = wn * 64 + nt * 8 + g;
                bf[nt][0] = ldh2(bs + n * 40 + kc);
                bf[nt][1] = ldh2(bs + n * 40 + kc + 8);
            }
#pragma unroll
            for (int mt = 0; mt < 4; mt++)
#pragma unroll
                for (int nt = 0; nt < 8; nt++)
                    mma_h(acc[mt][nt], af[mt], bf[nt]);
        }

        if (kb + 2 < nkb) ISSUE(kb + 2, (s + 2 >= GS) ? s - 1 : s + 2);
        s = (s + 1 == GS) ? 0 : s + 1;
    }

    // epilogue
#pragma unroll
    for (int mt = 0; mt < 4; mt++) {
        int r0 = mBase + wm * 64 + mt * 16 + g;
        float mk0 = rowmask ? rowmask[r0]     : 1.f;
        float mk1 = rowmask ? rowmask[r0 + 8] : 1.f;
#pragma unroll
        for (int nt = 0; nt < 8; nt++) {
            int c = nBase + wn * 64 + nt * 8 + 2 * tg;
            float b0 = bias ? bias[c]     : 0.f;
            float b1 = bias ? bias[c + 1] : 0.f;
            float v00 = (acc[mt][nt][0] + b0) * mk0;
            float v01 = (acc[mt][nt][1] + b1) * mk0;
            float v10 = (acc[mt][nt][2] + b0) * mk1;
            float v11 = (acc[mt][nt][3] + b1) * mk1;
            if (outHalf) {
                __half* Ch = (__half*)Cv;
                *(uint32_t*)(Ch + (size_t)r0 * ldc + c)       = packh2(v00, v01);
                *(uint32_t*)(Ch + (size_t)(r0 + 8) * ldc + c) = packh2(v10, v11);
            } else {
                float* Cf = (float*)Cv;
                *(float2*)(Cf + (size_t)r0 * ldc + c)       = make_float2(v00, v01);
                *(float2*)(Cf + (size_t)(r0 + 8) * ldc + c) = make_float2(v10, v11);
            }
        }
    }
}

// ================================================================================
// fp16 flash attention: O = softmax(Q K^T / sqrt(128)) V   per (b,h)
// BM=128 (8 warps x 16 rows), BN=64 kv chunk, DH=128.
// Q frags (half2) cached in regs; K/V double-buffered cp.async; V fragments via
// ldmatrix.x4.trans; P stored half; softmax math f32. Output fp16.
// smem (halves): K[2][64][136] (aliases 128x136 Q staging), V[2][64][136],
//                P[128][72]; mask f32 [2][64] after.
// ================================================================================
#define KST (64 * 136)
#define VST (64 * 136)
#define VOFF (2 * KST)
#define POFF (VOFF + 2 * VST)
#define MBYTE ((POFF + 128 * 72) * 2)          // byte offset of f32 mask region
#define ATTN_SMEMB (MBYTE + 2 * 64 * 4)

__global__ __launch_bounds__(256)
void attn_h(const __half* __restrict__ Q, const __half* __restrict__ KV,
            const float* __restrict__ smask, __half* __restrict__ O)
{
    extern __shared__ __half smh[];
    const uint32_t sb = smem_u32(smh);

    const int tid  = threadIdx.x;
    const int lane = tid & 31;
    const int w    = tid >> 5;
    const int g    = lane >> 2;
    const int tg   = lane & 3;

    const int bh = blockIdx.y;
    const int b  = bh >> 3;
    const int hh = bh & 7;
    const int t0 = blockIdx.x * 128;

    const __half* qg = Q + ((size_t)b * NSEQ + t0) * OUTD + hh * DHD;
    const __half* kg = KV + (size_t)b * NSEQ * (2 * OUTD) + hh * DHD;
    const __half* vg = kg + OUTD;
    const float*  mg = smask + (size_t)b * NSEQ;

    // ---- stage Q (128 rows x 128 halves) into smem (aliases K buffers) ----
#pragma unroll
    for (int i = 0; i < 8; i++) {
        int idx = tid + i * 256;
        int row = idx >> 4, c8 = idx & 15;          // 16 chunks of 8 halves
        *(uint4*)(smh + row * 136 + c8 * 8) =
            *(const uint4*)(qg + (size_t)row * OUTD + c8 * 8);
    }
    __syncthreads();

    // ---- cache Q fragments (8 k16 steps x 4 half2 regs) ----
    uint32_t qf[8][4];
    {
        const int r = w * 16 + g;
#pragma unroll
        for (int ks = 0; ks < 8; ks++) {
            const int kc = ks * 16 + 2 * tg;
            qf[ks][0] = ldh2(smh + r * 136 + kc);
            qf[ks][1] = ldh2(smh + (r + 8) * 136 + kc);
            qf[ks][2] = ldh2(smh + r * 136 + kc + 8);
            qf[ks][3] = ldh2(smh + (r + 8) * 136 + kc + 8);
        }
    }
    __syncthreads();

    // ---- cp.async loader: 64 rows x 16 chunks per operand per buffer ----
    auto ISSUE = [&](int j) {
        const int st = j & 1;
#pragma unroll
        for (int i = 0; i < 4; i++) {
            int idx = tid + i * 256;
            int row = idx >> 4, c = idx & 15;
            size_t go = (size_t)(j * 64 + row) * (2 * OUTD) + c * 8;
            cp16(sb + (st * KST + row * 136 + c * 8) * 2, kg + go);
            cp16(sb + (VOFF + st * VST + row * 136 + c * 8) * 2, vg + go);
        }
        if (tid < 16)
            cp16(sb + MBYTE + st * 256 + tid * 16, mg + j * 64 + tid * 4);
        cp_commit();
    };

    float oacc[16][4];
#pragma unroll
    for (int nt = 0; nt < 16; nt++)
#pragma unroll
        for (int i = 0; i < 4; i++) oacc[nt][i] = 0.f;
    float m0 = -1e30f, m1 = -1e30f, l0 = 0.f, l1 = 0.f;

    const float sc = 0.0883883476483184405f; // 1/sqrt(128)
    __half* p_s = smh + POFF;
    const int pr = w * 16 + g;
    // ldmatrix.trans per-lane address component (rows within 16-row s-group,
    // +8 halves for the d+8 matrices)
    const int vlane = (lane & 15) * 136 + ((lane & 16) ? 8 : 0);

    ISSUE(0);

    for (int j = 0; j < NSEQ / 64; j++) {
        const int st = j & 1;
        cp_wait0();
        __syncthreads();
        if (j + 1 < NSEQ / 64) ISSUE(j + 1);

        const __half* k_s = smh + st * KST;
        const float*  msk = (const float*)((const char*)smh + MBYTE + st * 256);
        const uint32_t vbase = sb + (VOFF + st * VST) * 2;

        // S = Q @ K^T  (8 k16 steps)
        float sacc[8][4];
#pragma unroll
        for (int nt = 0; nt < 8; nt++)
#pragma unroll
            for (int i = 0; i < 4; i++) sacc[nt][i] = 0.f;

#pragma unroll
        for (int ks = 0; ks < 8; ks++) {
            const int kc = ks * 16 + 2 * tg;
#pragma unroll
            for (int nt = 0; nt < 8; nt++) {
                int srow = nt * 8 + g;
                uint32_t bb[2];
                bb[0] = ldh2(k_s + srow * 136 + kc);
                bb[1] = ldh2(k_s + srow * 136 + kc + 8);
                mma_h(sacc[nt], qf[ks], bb);
            }
        }

        // scale + mask + row max
        float rmax0 = -1e30f, rmax1 = -1e30f;
#pragma unroll
        for (int nt = 0; nt < 8; nt++) {
#pragma unroll
            for (int i = 0; i < 4; i++) {
                float sv = sacc[nt][i] * sc;
                int col = nt * 8 + 2 * tg + (i & 1);
                if (msk[col] == 0.f) sv = -1e30f;
                sacc[nt][i] = sv;
                if (i < 2) rmax0 = fmaxf(rmax0, sv);
                else       rmax1 = fmaxf(rmax1, sv);
            }
        }
        rmax0 = fmaxf(rmax0, __shfl_xor_sync(0xffffffffu, rmax0, 1));
        rmax0 = fmaxf(rmax0, __shfl_xor_sync(0xffffffffu, rmax0, 2));
        rmax1 = fmaxf(rmax1, __shfl_xor_sync(0xffffffffu, rmax1, 1));
        rmax1 = fmaxf(rmax1, __shfl_xor_sync(0xffffffffu, rmax1, 2));

        float mn0 = fmaxf(m0, rmax0), mn1 = fmaxf(m1, rmax1);
        float cf0 = __expf(m0 - mn0), cf1 = __expf(m1 - mn1);
        m0 = mn0; m1 = mn1;

        // P = exp(S - m) -> half2 smem, rowsum
        float rs0 = 0.f, rs1 = 0.f;
#pragma unroll
        for (int nt = 0; nt < 8; nt++) {
            float p0 = __expf(sacc[nt][0] - mn0);
            float p1 = __expf(sacc[nt][1] - mn0);
            float p2 = __expf(sacc[nt][2] - mn1);
            float p3 = __expf(sacc[nt][3] - mn1);
            rs0 += p0 + p1; rs1 += p2 + p3;
            int pc = nt * 8 + 2 * tg;
            *(uint32_t*)(p_s + pr * 72 + pc)       = packh2(p0, p1);
            *(uint32_t*)(p_s + (pr + 8) * 72 + pc) = packh2(p2, p3);
        }
        rs0 += __shfl_xor_sync(0xffffffffu, rs0, 1);
        rs0 += __shfl_xor_sync(0xffffffffu, rs0, 2);
        rs1 += __shfl_xor_sync(0xffffffffu, rs1, 1);
        rs1 += __shfl_xor_sync(0xffffffffu, rs1, 2);
        l0 = l0 * cf0 + rs0;
        l1 = l1 * cf1 + rs1;

#pragma unroll
        for (int nt = 0; nt < 16; nt++) {
            oacc[nt][0] *= cf0; oacc[nt][1] *= cf0;
            oacc[nt][2] *= cf1; oacc[nt][3] *= cf1;
        }
        __syncwarp();

        // O += P @ V  (4 k16 steps over s, V frags via ldmatrix.x4.trans)
#pragma unroll
        for (int ks = 0; ks < 4; ks++) {
            const int kc = ks * 16 + 2 * tg;
            uint32_t pa[4];
            pa[0] = ldh2(p_s + pr * 72 + kc);
            pa[1] = ldh2(p_s + (pr + 8) * 72 + kc);
            pa[2] = ldh2(p_s + pr * 72 + kc + 8);
            pa[3] = ldh2(p_s + (pr + 8) * 72 + kc + 8);
            const uint32_t vrow = vbase + (ks * 16 * 136 + vlane) * 2;
#pragma unroll
            for (int dg = 0; dg < 8; dg++) {
                uint32_t r0, r1, r2, r3;
                ldsm_x4_t(r0, r1, r2, r3, vrow + dg * 32);
                uint32_t b0[2] = {r0, r1}, b1[2] = {r2, r3};
                mma_h(oacc[2 * dg],     pa, b0);
                mma_h(oacc[2 * dg + 1], pa, b1);
            }
        }
    }

    // write out fp16 (feeds the fused out-GEMM)
    float inv0 = 1.f / l0, inv1 = 1.f / l1;
    const int tr0 = t0 + w * 16 + g;
    __half* og = O + (size_t)b * NSEQ * OUTD + hh * DHD;
#pragma unroll
    for (int nt = 0; nt < 16; nt++) {
        int dc = nt * 8 + 2 * tg;
        *(uint32_t*)(og + (size_t)tr0 * OUTD + dc) =
            packh2(oacc[nt][0] * inv0, oacc[nt][1] * inv0);
        *(uint32_t*)(og + (size_t)(tr0 + 8) * OUTD + dc) =
            packh2(oacc[nt][2] * inv1, oacc[nt][3] * inv1);
    }
}

// ================================================================================
// launch
// ================================================================================
extern "C" void kernel_launch(void* const* d_in, const int* in_sizes, int n_in,
                              void* d_out, int out_size)
{
    const float* src      = (const float*)d_in[0];
    const float* tgt      = (const float*)d_in[1];
    const float* src_mask = (const float*)d_in[2];
    const float* tgt_mask = (const float*)d_in[3];
    const float* Ws       = (const float*)d_in[4];
    const float* bs       = (const float*)d_in[5];
    const float* Wt       = (const float*)d_in[6];
    const float* bt       = (const float*)d_in[7];
    const float* Wo       = (const float*)d_in[8];
    const float* bo       = (const float*)d_in[9];
    float* out = (float*)d_out;

    __half *kv, *q, *upd, *hsrc, *htgt, *hws, *hwt, *hwo;
    cudaGetSymbolAddress((void**)&kv,   h_kv);
    cudaGetSymbolAddress((void**)&q,    h_q);
    cudaGetSymbolAddress((void**)&upd,  h_upd);
    cudaGetSymbolAddress((void**)&hsrc, h_src);
    cudaGetSymbolAddress((void**)&htgt, h_tgt);
    cudaGetSymbolAddress((void**)&hws,  h_ws);
    cudaGetSymbolAddress((void**)&hwt,  h_wt);
    cudaGetSymbolAddress((void**)&hwo,  h_wo);

    const int gSmem = GS * STGB;               // 61440
    const int aSmem = ATTN_SMEMB;              // ~89KB
    cudaFuncSetAttribute(gemm_h, cudaFuncAttributeMaxDynamicSharedMemorySize, gSmem);
    cudaFuncSetAttribute(attn_h, cudaFuncAttributeMaxDynamicSharedMemorySize, aSmem);

    // 0) f32 -> fp16 conversion of all inputs
    f2h<<<(8*1024*1024/8 + 255) / 256, 256>>>((const float4*)src, (uint4*)hsrc, 8*1024*1024/8);
    f2h<<<(8*1024*1024/8 + 255) / 256, 256>>>((const float4*)tgt, (uint4*)htgt, 8*1024*1024/8);
    f2h<<<(2*1024*1024/8 + 255) / 256, 256>>>((const float4*)Ws,  (uint4*)hws,  2*1024*1024/8);
    f2h<<<(1024*1024/8   + 255) / 256, 256>>>((const float4*)Wt,  (uint4*)hwt,  1024*1024/8);
    f2h<<<(2*1024*1024/8 + 255) / 256, 256>>>((const float4*)Wo,  (uint4*)hwo,  2*1024*1024/8);

    const int M = Bsz * NSEQ; // 8192

    // 1) kv = src @ Ws^T + bs, *src_mask   -> fp16 [8192, 2048]
    gemm_h<<<dim3(2048 / 128, M / 128), 128, gSmem>>>(
        hsrc, hsrc, hws, 1024, bs, src_mask, kv, 2048, 32, 1);

    // 2) q = tgt @ Wt^T + bt, *tgt_mask    -> fp16 [8192, 1024]
    gemm_h<<<dim3(1024 / 128, M / 128), 128, gSmem>>>(
        htgt, htgt, hwt, 1024, bt, tgt_mask, q, 1024, 32, 1);

    // 3) flash attention -> upd fp16       [8192, 1024]
    attn_h<<<dim3(NSEQ / 128, Bsz * 8), 256, aSmem>>>(q, kv, src_mask, upd);

    // 4) out = [tgt | upd] @ Wo^T + bo  (fused K=2048) -> f32
    gemm_h<<<dim3(1024 / 128, M / 128), 128, gSmem>>>(
        htgt, upd, hwo, 2048, bo, nullptr, out, 1024, 64, 0);
}

// round 8
// speedup vs baseline: 2.2932x; 1.0026x over previous
#include <cuda_runtime.h>
#include <cuda_fp16.h>
#include <cstdint>

#define Bsz 8
#define NSEQ 1024
#define OUTD 1024
#define DHD 128

#define DINLINE __device__ __forceinline__

// ---------------- scratch (allocation-free rule: __device__ globals) ----------
__device__ __align__(16) __half h_kv [8u*1024u*2048u];   // src_trans half [B*NS,2048]
__device__ __align__(16) __half h_q  [8u*1024u*1024u];   // tgt_trans half
__device__ __align__(16) __half h_upd[8u*1024u*1024u];   // tgt_update half
__device__ __align__(16) __half h_src[8u*1024u*1024u];   // fp16 inputs
__device__ __align__(16) __half h_tgt[8u*1024u*1024u];
__device__ __align__(16) __half h_ws [2u*1024u*1024u];
__device__ __align__(16) __half h_wt [1024u*1024u];
__device__ __align__(16) __half h_wo [2u*1024u*1024u];

// ---------------- helpers ------------------------------------------------------
DINLINE uint32_t smem_u32(const void* p) {
    uint32_t a;
    asm("{ .reg .u64 t; cvta.to.shared.u64 t, %1; cvt.u32.u64 %0, t; }" : "=r"(a) : "l"(p));
    return a;
}
DINLINE void cp16(uint32_t dst, const void* src) {
    asm volatile("cp.async.cg.shared.global [%0], [%1], 16;" :: "r"(dst), "l"(src) : "memory");
}
DINLINE void cp_commit() { asm volatile("cp.async.commit_group;" ::: "memory"); }
DINLINE void cp_wait0()  { asm volatile("cp.async.wait_group 0;" ::: "memory"); }
DINLINE void cp_wait1()  { asm volatile("cp.async.wait_group 1;" ::: "memory"); }
DINLINE void cp_wait2()  { asm volatile("cp.async.wait_group 2;" ::: "memory"); }

DINLINE void mma_h(float c[4], const uint32_t a[4], const uint32_t b[2]) {
    asm volatile(
        "mma.sync.aligned.m16n8k16.row.col.f32.f16.f16.f32 "
        "{%0,%1,%2,%3}, {%4,%5,%6,%7}, {%8,%9}, {%0,%1,%2,%3};"
        : "+f"(c[0]), "+f"(c[1]), "+f"(c[2]), "+f"(c[3])
        : "r"(a[0]), "r"(a[1]), "r"(a[2]), "r"(a[3]), "r"(b[0]), "r"(b[1]));
}

DINLINE void ldsm_x4(uint32_t& r0, uint32_t& r1, uint32_t& r2, uint32_t& r3, uint32_t a) {
    asm volatile("ldmatrix.sync.aligned.m8n8.x4.shared.b16 {%0,%1,%2,%3}, [%4];"
                 : "=r"(r0), "=r"(r1), "=r"(r2), "=r"(r3) : "r"(a));
}
DINLINE void ldsm_x4_t(uint32_t& r0, uint32_t& r1, uint32_t& r2, uint32_t& r3, uint32_t a) {
    asm volatile("ldmatrix.sync.aligned.m8n8.x4.trans.shared.b16 {%0,%1,%2,%3}, [%4];"
                 : "=r"(r0), "=r"(r1), "=r"(r2), "=r"(r3) : "r"(a));
}

DINLINE uint32_t ldh2(const __half* p) { return *(const uint32_t*)p; }
DINLINE uint32_t packh2(float x, float y) {
    __half2 h = __floats2half2_rn(x, y);
    return *reinterpret_cast<uint32_t*>(&h);
}

// ================================================================================
// f32 -> fp16 conversion pre-pass
// ================================================================================
__global__ void f2h(const float4* __restrict__ in, uint4* __restrict__ out, int n8)
{
    int i = blockIdx.x * blockDim.x + threadIdx.x;
    if (i < n8) {
        float4 a = in[2 * i], b = in[2 * i + 1];
        uint4 o;
        o.x = packh2(a.x, a.y);
        o.y = packh2(a.z, a.w);
        o.z = packh2(b.x, b.y);
        o.w = packh2(b.z, b.w);
        out[i] = o;
    }
}

// ================================================================================
// fp16 GEMM: C[M,N] = [A0|A1][M,K] @ W[N,K]^T (+bias f32) (*rowmask f32)
// BM=BN=128, BK=32. 128 threads, 4 warps (2m x 2n), warp tile 64x64.
// ldmatrix.x4 fragment loads (conflict-free with pad-40 rows), 4-stage cp.async.
// ================================================================================
#define GS 4
#define STGH (2 * 128 * 40)          // halves per stage (A then B)
#define STGB (STGH * 2)              // 20480 bytes

__global__ __launch_bounds__(128, 2)
void gemm_h(const __half* __restrict__ A0, const __half* __restrict__ A1,
            const __half* __restrict__ W, int ldw,
            const float* __restrict__ bias, const float* __restrict__ rowmask,
            void* __restrict__ Cv, int ldc, int nkb, int outHalf)
{
    extern __shared__ __half smh[];
    const uint32_t sb = smem_u32(smh);

    const int tid  = threadIdx.x;
    const int lane = tid & 31;
    const int wid  = tid >> 5;
    const int wm   = wid & 1;
    const int wn   = wid >> 1;
    const int g    = lane >> 2;
    const int tg   = lane & 3;

    const int mBase = blockIdx.y * 128;
    const int nBase = blockIdx.x * 128;

    // cp.async: tile = 128 rows x 32 halves; 4 x 16B per operand per thread
    uint32_t dOf[4];
    int aOf[4], wOf[4];
#pragma unroll
    for (int i = 0; i < 4; i++) {
        int idx = tid + i * 128;
        int row = idx >> 2, c = idx & 3;
        dOf[i] = row * 80 + c * 16;
        aOf[i] = (mBase + row) * 1024 + c * 8;
        wOf[i] = (nBase + row) * ldw + c * 8;
    }

    auto ISSUE = [&](int kb) {
        const int s = kb & 3;
        const int kg = kb * 32;
        const __half* Ap = (kg < 1024) ? A0 : A1;
        const int ka = kg & 1023;
        const uint32_t sa  = sb + s * STGB;
        const uint32_t sbb = sa + 128 * 80;
#pragma unroll
        for (int i = 0; i < 4; i++) cp16(sa  + dOf[i], Ap + aOf[i] + ka);
#pragma unroll
        for (int i = 0; i < 4; i++) cp16(sbb + dOf[i], W  + wOf[i] + kg);
        cp_commit();
    };

    // ldmatrix per-lane byte offsets (row stride 80B)
    const uint32_t aLn = (lane & 15) * 80 + ((lane & 16) ? 16u : 0u);
    const uint32_t bLn = (lane & 7) * 80 + ((lane & 16) ? 8u * 80u : 0u) + ((lane & 8) ? 16u : 0u);

    float acc[4][8][4];
#pragma unroll
    for (int mt = 0; mt < 4; mt++)
#pragma unroll
        for (int nt = 0; nt < 8; nt++)
#pragma unroll
            for (int i = 0; i < 4; i++) acc[mt][nt][i] = 0.f;

    ISSUE(0); ISSUE(1); ISSUE(2);

    for (int kb = 0; kb < nkb; kb++) {
        if (kb < nkb - 2)      cp_wait2();
        else if (kb < nkb - 1) cp_wait1();
        else                   cp_wait0();
        __syncthreads();

        const uint32_t saA = sb + (kb & 3) * STGB;
        const uint32_t saB = saA + 128 * 80;
#pragma unroll
        for (int ks = 0; ks < 2; ks++) {
            const uint32_t aBase = saA + (uint32_t)(wm * 64) * 80 + ks * 32 + aLn;
            const uint32_t bBase = saB + (uint32_t)(wn * 64) * 80 + ks * 32 + bLn;
            uint32_t af[4][4], bf[8][2];
#pragma unroll
            for (int mt = 0; mt < 4; mt++)
                ldsm_x4(af[mt][0], af[mt][1], af[mt][2], af[mt][3], aBase + mt * 16 * 80);
#pragma unroll
            for (int p = 0; p < 4; p++)
                ldsm_x4(bf[2*p][0], bf[2*p][1], bf[2*p+1][0], bf[2*p+1][1], bBase + p * 16 * 80);
#pragma unroll
            for (int mt = 0; mt < 4; mt++)
#pragma unroll
                for (int nt = 0; nt < 8; nt++)
                    mma_h(acc[mt][nt], af[mt], bf[nt]);
        }

        __syncthreads();
        if (kb + 3 < nkb) ISSUE(kb + 3);
    }

    // epilogue
#pragma unroll
    for (int mt = 0; mt < 4; mt++) {
        int r0 = mBase + wm * 64 + mt * 16 + g;
        float mk0 = rowmask ? rowmask[r0]     : 1.f;
        float mk1 = rowmask ? rowmask[r0 + 8] : 1.f;
#pragma unroll
        for (int nt = 0; nt < 8; nt++) {
            int c = nBase + wn * 64 + nt * 8 + 2 * tg;
            float b0 = bias ? bias[c]     : 0.f;
            float b1 = bias ? bias[c + 1] : 0.f;
            float v00 = (acc[mt][nt][0] + b0) * mk0;
            float v01 = (acc[mt][nt][1] + b1) * mk0;
            float v10 = (acc[mt][nt][2] + b0) * mk1;
            float v11 = (acc[mt][nt][3] + b1) * mk1;
            if (outHalf) {
                __half* Ch = (__half*)Cv;
                *(uint32_t*)(Ch + (size_t)r0 * ldc + c)       = packh2(v00, v01);
                *(uint32_t*)(Ch + (size_t)(r0 + 8) * ldc + c) = packh2(v10, v11);
            } else {
                float* Cf = (float*)Cv;
                *(float2*)(Cf + (size_t)r0 * ldc + c)       = make_float2(v00, v01);
                *(float2*)(Cf + (size_t)(r0 + 8) * ldc + c) = make_float2(v10, v11);
            }
        }
    }
}

// ================================================================================
// fp16 flash attention — R7 structure; K fragments now via ldmatrix.x4.
// ================================================================================
#define KST (64 * 136)
#define VST (64 * 136)
#define VOFF (2 * KST)
#define POFF (VOFF + 2 * VST)
#define MBYTE ((POFF + 128 * 72) * 2)
#define ATTN_SMEMB (MBYTE + 2 * 64 * 4)

__global__ __launch_bounds__(256)
void attn_h(const __half* __restrict__ Q, const __half* __restrict__ KV,
            const float* __restrict__ smask, __half* __restrict__ O)
{
    extern __shared__ __half smh[];
    const uint32_t sb = smem_u32(smh);

    const int tid  = threadIdx.x;
    const int lane = tid & 31;
    const int w    = tid >> 5;
    const int g    = lane >> 2;
    const int tg   = lane & 3;

    const int bh = blockIdx.y;
    const int b  = bh >> 3;
    const int hh = bh & 7;
    const int t0 = blockIdx.x * 128;

    const __half* qg = Q + ((size_t)b * NSEQ + t0) * OUTD + hh * DHD;
    const __half* kg = KV + (size_t)b * NSEQ * (2 * OUTD) + hh * DHD;
    const __half* vg = kg + OUTD;
    const float*  mg = smask + (size_t)b * NSEQ;

    // ---- stage Q (128 x 128 halves), alias K buffers ----
#pragma unroll
    for (int i = 0; i < 8; i++) {
        int idx = tid + i * 256;
        int row = idx >> 4, c8 = idx & 15;
        *(uint4*)(smh + row * 136 + c8 * 8) =
            *(const uint4*)(qg + (size_t)row * OUTD + c8 * 8);
    }
    __syncthreads();

    uint32_t qf[8][4];
    {
        const int r = w * 16 + g;
#pragma unroll
        for (int ks = 0; ks < 8; ks++) {
            const int kc = ks * 16 + 2 * tg;
            qf[ks][0] = ldh2(smh + r * 136 + kc);
            qf[ks][1] = ldh2(smh + (r + 8) * 136 + kc);
            qf[ks][2] = ldh2(smh + r * 136 + kc + 8);
            qf[ks][3] = ldh2(smh + (r + 8) * 136 + kc + 8);
        }
    }
    __syncthreads();

    auto ISSUE = [&](int j) {
        const int st = j & 1;
#pragma unroll
        for (int i = 0; i < 4; i++) {
            int idx = tid + i * 256;
            int row = idx >> 4, c = idx & 15;
            size_t go = (size_t)(j * 64 + row) * (2 * OUTD) + c * 8;
            cp16(sb + (st * KST + row * 136 + c * 8) * 2, kg + go);
            cp16(sb + (VOFF + st * VST + row * 136 + c * 8) * 2, vg + go);
        }
        if (tid < 16)
            cp16(sb + MBYTE + st * 256 + tid * 16, mg + j * 64 + tid * 4);
        cp_commit();
    };

    float oacc[16][4];
#pragma unroll
    for (int nt = 0; nt < 16; nt++)
#pragma unroll
        for (int i = 0; i < 4; i++) oacc[nt][i] = 0.f;
    float m0 = -1e30f, m1 = -1e30f, l0 = 0.f, l1 = 0.f;

    const float sc = 0.0883883476483184405f; // 1/sqrt(128)
    __half* p_s = smh + POFF;
    const int pr = w * 16 + g;
    const int vlane = (lane & 15) * 136 + ((lane & 16) ? 8 : 0);
    // K ldmatrix lane offset (row stride 272B)
    const uint32_t kLn = (lane & 7) * 272 + ((lane & 16) ? 8u * 272u : 0u) + ((lane & 8) ? 16u : 0u);

    ISSUE(0);

    for (int j = 0; j < NSEQ / 64; j++) {
        const int st = j & 1;
        cp_wait0();
        __syncthreads();
        if (j + 1 < NSEQ / 64) ISSUE(j + 1);

        const float*  msk = (const float*)((const char*)smh + MBYTE + st * 256);
        const uint32_t kbase = sb + (st * KST) * 2;
        const uint32_t vbase = sb + (VOFF + st * VST) * 2;

        // S = Q @ K^T
        float sacc[8][4];
#pragma unroll
        for (int nt = 0; nt < 8; nt++)
#pragma unroll
            for (int i = 0; i < 4; i++) sacc[nt][i] = 0.f;

#pragma unroll
        for (int ks = 0; ks < 8; ks++) {
            const uint32_t bBase = kbase + ks * 32 + kLn;
            uint32_t bf[8][2];
#pragma unroll
            for (int p = 0; p < 4; p++)
                ldsm_x4(bf[2*p][0], bf[2*p][1], bf[2*p+1][0], bf[2*p+1][1], bBase + p * 16 * 272);
#pragma unroll
            for (int nt = 0; nt < 8; nt++)
                mma_h(sacc[nt], qf[ks], bf[nt]);
        }

        // scale + mask + row max
        float rmax0 = -1e30f, rmax1 = -1e30f;
#pragma unroll
        for (int nt = 0; nt < 8; nt++) {
#pragma unroll
            for (int i = 0; i < 4; i++) {
                float sv = sacc[nt][i] * sc;
                int col = nt * 8 + 2 * tg + (i & 1);
                if (msk[col] == 0.f) sv = -1e30f;
                sacc[nt][i] = sv;
                if (i < 2) rmax0 = fmaxf(rmax0, sv);
                else       rmax1 = fmaxf(rmax1, sv);
            }
        }
        rmax0 = fmaxf(rmax0, __shfl_xor_sync(0xffffffffu, rmax0, 1));
        rmax0 = fmaxf(rmax0, __shfl_xor_sync(0xffffffffu, rmax0, 2));
        rmax1 = fmaxf(rmax1, __shfl_xor_sync(0xffffffffu, rmax1, 1));
        rmax1 = fmaxf(rmax1, __shfl_xor_sync(0xffffffffu, rmax1, 2));

        float mn0 = fmaxf(m0, rmax0), mn1 = fmaxf(m1, rmax1);
        float cf0 = __expf(m0 - mn0), cf1 = __expf(m1 - mn1);
        m0 = mn0; m1 = mn1;

        float rs0 = 0.f, rs1 = 0.f;
#pragma unroll
        for (int nt = 0; nt < 8; nt++) {
            float p0 = __expf(sacc[nt][0] - mn0);
            float p1 = __expf(sacc[nt][1] - mn0);
            float p2 = __expf(sacc[nt][2] - mn1);
            float p3 = __expf(sacc[nt][3] - mn1);
            rs0 += p0 + p1; rs1 += p2 + p3;
            int pc = nt * 8 + 2 * tg;
            *(uint32_t*)(p_s + pr * 72 + pc)       = packh2(p0, p1);
            *(uint32_t*)(p_s + (pr + 8) * 72 + pc) = packh2(p2, p3);
        }
        rs0 += __shfl_xor_sync(0xffffffffu, rs0, 1);
        rs0 += __shfl_xor_sync(0xffffffffu, rs0, 2);
        rs1 += __shfl_xor_sync(0xffffffffu, rs1, 1);
        rs1 += __shfl_xor_sync(0xffffffffu, rs1, 2);
        l0 = l0 * cf0 + rs0;
        l1 = l1 * cf1 + rs1;

#pragma unroll
        for (int nt = 0; nt < 16; nt++) {
            oacc[nt][0] *= cf0; oacc[nt][1] *= cf0;
            oacc[nt][2] *= cf1; oacc[nt][3] *= cf1;
        }
        __syncwarp();

        // O += P @ V
#pragma unroll
        for (int ks = 0; ks < 4; ks++) {
            const int kc = ks * 16 + 2 * tg;
            uint32_t pa[4];
            pa[0] = ldh2(p_s + pr * 72 + kc);
            pa[1] = ldh2(p_s + (pr + 8) * 72 + kc);
            pa[2] = ldh2(p_s + pr * 72 + kc + 8);
            pa[3] = ldh2(p_s + (pr + 8) * 72 + kc + 8);
            const uint32_t vrow = vbase + (ks * 16 * 136 + vlane) * 2;
#pragma unroll
            for (int dg = 0; dg < 8; dg++) {
                uint32_t r0, r1, r2, r3;
                ldsm_x4_t(r0, r1, r2, r3, vrow + dg * 32);
                uint32_t b0[2] = {r0, r1}, b1[2] = {r2, r3};
                mma_h(oacc[2 * dg],     pa, b0);
                mma_h(oacc[2 * dg + 1], pa, b1);
            }
        }
    }

    float inv0 = 1.f / l0, inv1 = 1.f / l1;
    const int tr0 = t0 + w * 16 + g;
    __half* og = O + (size_t)b * NSEQ * OUTD + hh * DHD;
#pragma unroll
    for (int nt = 0; nt < 16; nt++) {
        int dc = nt * 8 + 2 * tg;
        *(uint32_t*)(og + (size_t)tr0 * OUTD + dc) =
            packh2(oacc[nt][0] * inv0, oacc[nt][1] * inv0);
        *(uint32_t*)(og + (size_t)(tr0 + 8) * OUTD + dc) =
            packh2(oacc[nt][2] * inv1, oacc[nt][3] * inv1);
    }
}

// ================================================================================
// launch
// ================================================================================
extern "C" void kernel_launch(void* const* d_in, const int* in_sizes, int n_in,
                              void* d_out, int out_size)
{
    const float* src      = (const float*)d_in[0];
    const float* tgt      = (const float*)d_in[1];
    const float* src_mask = (const float*)d_in[2];
    const float* tgt_mask = (const float*)d_in[3];
    const float* Ws       = (const float*)d_in[4];
    const float* bs       = (const float*)d_in[5];
    const float* Wt       = (const float*)d_in[6];
    const float* bt       = (const float*)d_in[7];
    const float* Wo       = (const float*)d_in[8];
    const float* bo       = (const float*)d_in[9];
    float* out = (float*)d_out;

    __half *kv, *q, *upd, *hsrc, *htgt, *hws, *hwt, *hwo;
    cudaGetSymbolAddress((void**)&kv,   h_kv);
    cudaGetSymbolAddress((void**)&q,    h_q);
    cudaGetSymbolAddress((void**)&upd,  h_upd);
    cudaGetSymbolAddress((void**)&hsrc, h_src);
    cudaGetSymbolAddress((void**)&htgt, h_tgt);
    cudaGetSymbolAddress((void**)&hws,  h_ws);
    cudaGetSymbolAddress((void**)&hwt,  h_wt);
    cudaGetSymbolAddress((void**)&hwo,  h_wo);

    const int gSmem = GS * STGB;               // 81920
    const int aSmem = ATTN_SMEMB;              // ~89KB
    cudaFuncSetAttribute(gemm_h, cudaFuncAttributeMaxDynamicSharedMemorySize, gSmem);
    cudaFuncSetAttribute(attn_h, cudaFuncAttributeMaxDynamicSharedMemorySize, aSmem);

    // 0) f32 -> fp16 conversion of all inputs
    f2h<<<(8*1024*1024/8 + 255) / 256, 256>>>((const float4*)src, (uint4*)hsrc, 8*1024*1024/8);
    f2h<<<(8*1024*1024/8 + 255) / 256, 256>>>((const float4*)tgt, (uint4*)htgt, 8*1024*1024/8);
    f2h<<<(2*1024*1024/8 + 255) / 256, 256>>>((const float4*)Ws,  (uint4*)hws,  2*1024*1024/8);
    f2h<<<(1024*1024/8   + 255) / 256, 256>>>((const float4*)Wt,  (uint4*)hwt,  1024*1024/8);
    f2h<<<(2*1024*1024/8 + 255) / 256, 256>>>((const float4*)Wo,  (uint4*)hwo,  2*1024*1024/8);

    const int M = Bsz * NSEQ; // 8192

    // 1) kv = src @ Ws^T + bs, *src_mask   -> fp16 [8192, 2048]
    gemm_h<<<dim3(2048 / 128, M / 128), 128, gSmem>>>(
        hsrc, hsrc, hws, 1024, bs, src_mask, kv, 2048, 32, 1);

    // 2) q = tgt @ Wt^T + bt, *tgt_mask    -> fp16 [8192, 1024]
    gemm_h<<<dim3(1024 / 128, M / 128), 128, gSmem>>>(
        htgt, htgt, hwt, 1024, bt, tgt_mask, q, 1024, 32, 1);

    // 3) flash attention -> upd fp16       [8192, 1024]
    attn_h<<<dim3(NSEQ / 128, Bsz * 8), 256, aSmem>>>(q, kv, src_mask, upd);

    // 4) out = [tgt | upd] @ Wo^T + bo  (fused K=2048) -> f32
    gemm_h<<<dim3(1024 / 128, M / 128), 128, gSmem>>>(
        htgt, upd, hwo, 2048, bo, nullptr, out, 1024, 64, 0);
}